// round 14
// baseline (speedup 1.0000x reference)
#include <cuda_runtime.h>
#include <cuda_bf16.h>
#include <cstdint>

#define NTOK 16384
#define DIM  1024
#define FF   4096
#define NE   8
#define CAP  2560
#define NBM  20            // CAP / 128
#define BK   64
#define NIT1 (DIM / BK)    // 16
#define NIT2 (FF / BK)     // 64
#define ST1  49152         // stage bytes gemm1: A 16K + Bg 16K + Bu 16K
#define ST2  49152         // stage bytes gemm2: A 16K + B 32K
#define NRB  (NTOK / 8)    // router blocks = 2048

// ---------------- scratch globals -------------------------------------------
__device__ __nv_bfloat16 g_xb[(size_t)NTOK * DIM];
__device__ __nv_bfloat16 g_wgT[(size_t)NE * FF * DIM];  // [E][F][D]
__device__ __nv_bfloat16 g_wuT[(size_t)NE * FF * DIM];  // [E][F][D]
__device__ __nv_bfloat16 g_wdT[(size_t)NE * DIM * FF];  // [E][D][F]
__device__ __nv_bfloat16 g_h[(size_t)NE * CAP * FF];
__device__ float g_ffn[(size_t)NTOK * DIM];
__device__ int   g_top1[NTOK];
__device__ float g_topv[NTOK];
__device__ int   g_dest[NE * CAP];
__device__ int   g_rows[NE];
__device__ int   g_cnt[NE];
__device__ float g_sumP[NE];
__device__ float g_blockP[NRB][NE];

// ---------------- PTX helpers ------------------------------------------------
__device__ __forceinline__ uint32_t s2u(const void* p) {
    return (uint32_t)__cvta_generic_to_shared(p);
}
__device__ __forceinline__ void cp16(uint32_t dst, const void* src) {
    asm volatile("cp.async.cg.shared.global [%0], [%1], 16;\n" :: "r"(dst), "l"(src));
}
__device__ __forceinline__ void cp_commit() { asm volatile("cp.async.commit_group;\n" ::: "memory"); }
__device__ __forceinline__ void cp_wait0()  { asm volatile("cp.async.wait_group 0;\n" ::: "memory"); }
__device__ __forceinline__ void cp_wait1()  { asm volatile("cp.async.wait_group 1;\n" ::: "memory"); }

__device__ __forceinline__ void ldsm4(uint32_t (&d)[4], uint32_t addr) {
    asm volatile("ldmatrix.sync.aligned.m8n8.x4.shared.b16 {%0,%1,%2,%3}, [%4];"
        : "=r"(d[0]), "=r"(d[1]), "=r"(d[2]), "=r"(d[3]) : "r"(addr));
}
__device__ __forceinline__ void mma16816(float (&c)[4], const uint32_t (&a)[4],
                                         uint32_t b0, uint32_t b1) {
    asm volatile("mma.sync.aligned.m16n8k16.row.col.f32.bf16.bf16.f32 "
        "{%0,%1,%2,%3}, {%4,%5,%6,%7}, {%8,%9}, {%0,%1,%2,%3};"
        : "+f"(c[0]), "+f"(c[1]), "+f"(c[2]), "+f"(c[3])
        : "r"(a[0]), "r"(a[1]), "r"(a[2]), "r"(a[3]), "r"(b0), "r"(b1));
}

// ---------------- anchor (capture origin) ------------------------------------
__global__ void k_anchor() {}

// ---------------- transpose: fp32 [E][R][C] -> bf16 [E][C][R] ------------------
__global__ void __launch_bounds__(256) k_transpose(const float* __restrict__ in,
                                                   __nv_bfloat16* __restrict__ out,
                                                   int R, int C) {
    __shared__ float tile[32][33];
    int e = blockIdx.z;
    int c0 = blockIdx.x * 32, r0 = blockIdx.y * 32;
    int tx = threadIdx.x & 31, ty = threadIdx.x >> 5;
    const float* src = in + (size_t)e * R * C;
    __nv_bfloat16* dst = out + (size_t)e * C * R;
#pragma unroll
    for (int k = 0; k < 4; k++)
        tile[ty + 8 * k][tx] = src[(size_t)(r0 + ty + 8 * k) * C + c0 + tx];
    __syncthreads();
#pragma unroll
    for (int k = 0; k < 4; k++)
        dst[(size_t)(c0 + ty + 8 * k) * R + r0 + tx] = __float2bfloat16(tile[tx][ty + 8 * k]);
}

// ---------------- router (converts x -> bf16, zeroes g_ffn rows) --------------
__global__ void __launch_bounds__(256) k_router(const float* __restrict__ x,
                                                const float* __restrict__ rw) {
    __shared__ float rwsT[NE][DIM];    // transposed: conflict-free float4 reads
    __shared__ float blockP[NE];
    int tid = threadIdx.x;
    for (int i = tid; i < DIM * NE; i += 256) {
        int d = i >> 3, e = i & 7;
        rwsT[e][d] = rw[i];
    }
    if (tid < NE) blockP[tid] = 0.f;
    __syncthreads();

    int warp = tid >> 5, lane = tid & 31;
    int token = blockIdx.x * 8 + warp;

    float acc[NE];
#pragma unroll
    for (int e = 0; e < NE; e++) acc[e] = 0.f;
    const float* xr = x + (size_t)token * DIM;
    __nv_bfloat16* xb = g_xb + (size_t)token * DIM;
    float* fz = g_ffn + (size_t)token * DIM;
    float4 z4 = make_float4(0.f, 0.f, 0.f, 0.f);
    for (int i = lane * 4; i < DIM; i += 128) {
        float4 v = *(const float4*)(xr + i);
        *(__nv_bfloat162*)(xb + i)     = __floats2bfloat162_rn(v.x, v.y);
        *(__nv_bfloat162*)(xb + i + 2) = __floats2bfloat162_rn(v.z, v.w);
        *(float4*)(fz + i) = z4;
#pragma unroll
        for (int e = 0; e < NE; e++) {
            float4 w = *(const float4*)(&rwsT[e][i]);
            acc[e] += v.x * w.x + v.y * w.y + v.z * w.z + v.w * w.w;
        }
    }
#pragma unroll
    for (int e = 0; e < NE; e++)
#pragma unroll
        for (int o = 16; o; o >>= 1) acc[e] += __shfl_xor_sync(0xffffffffu, acc[e], o);

    if (lane == 0) {
        float m = acc[0]; int am = 0;
#pragma unroll
        for (int e = 1; e < NE; e++) if (acc[e] > m) { m = acc[e]; am = e; }
        float p[NE], s = 0.f;
#pragma unroll
        for (int e = 0; e < NE; e++) { p[e] = __expf(acc[e] - m); s += p[e]; }
        float inv = 1.f / s;
        g_top1[token] = am;
        g_topv[token] = p[am] * inv;
#pragma unroll
        for (int e = 0; e < NE; e++) atomicAdd(&blockP[e], p[e] * inv);
    }
    __syncthreads();
    if (tid < NE) g_blockP[blockIdx.x][tid] = blockP[tid];
}

// ---------------- deterministic scan + prob-sum reduction --------------------
__global__ void k_scan() {
    __shared__ int base[NE];
    __shared__ int wcnt[8][NE];
    int tid = threadIdx.x;
    int warp = tid >> 5, lane = tid & 31;
    unsigned ltmask = (1u << lane) - 1u;

    if (warp < NE) {
        float s = 0.f;
        for (int b = lane; b < NRB; b += 32) s += g_blockP[b][warp];
#pragma unroll
        for (int o = 16; o; o >>= 1) s += __shfl_xor_sync(0xffffffffu, s, o);
        if (lane == 0) g_sumP[warp] = s;
    }

    if (tid < NE) base[tid] = 0;
    __syncthreads();
    for (int w = 0; w < NTOK / 256; w++) {
        int t = w * 256 + tid;
        int e = g_top1[t];
        int myrank = 0;
#pragma unroll
        for (int ee = 0; ee < NE; ee++) {
            unsigned b = __ballot_sync(0xffffffffu, e == ee);
            if (lane == ee) wcnt[warp][ee] = __popc(b);
            if (e == ee) myrank = __popc(b & ltmask);
        }
        __syncthreads();
        int off = base[e];
        for (int w2 = 0; w2 < warp; w2++) off += wcnt[w2][e];
        int p = off + myrank;
        if (p < CAP) g_dest[e * CAP + p] = t;
        __syncthreads();
        if (tid < NE) {
            int s = 0;
#pragma unroll
            for (int w2 = 0; w2 < 8; w2++) s += wcnt[w2][tid];
            base[tid] += s;
        }
        __syncthreads();
    }
    if (tid < NE) {
        g_cnt[tid] = base[tid];
        g_rows[tid] = min(base[tid], CAP);
    }
}

// ---------------- GEMM1: mma.sync, 3-stage (R12 config) ----------------------
// CTA: M=128 x N=128 (both), 512 threads; warps 0-7 gate, 8-15 up; 64x32 tiles
__global__ void __launch_bounds__(512, 1) k_gemm1() {
    extern __shared__ char smem[];
    __shared__ const __nv_bfloat16* tokp[128];

    int e = blockIdx.x / NBM;
    int m0 = (blockIdx.x % NBM) * 128;
    int rows = g_rows[e];
    if (m0 >= rows) return;
    int n0 = blockIdx.y * 128;
    int tid = threadIdx.x;
    int wid = tid >> 5, l = tid & 31;

    if (tid < 128) {
        int gr = m0 + tid;
        tokp[tid] = g_xb + (size_t)g_dest[e * CAP + ((gr < rows) ? gr : 0)] * DIM;
    }
    __syncthreads();

    uint32_t sb = s2u(smem);
    const __nv_bfloat16* gB = g_wgT + (size_t)e * FF * DIM + (size_t)n0 * DIM;
    const __nv_bfloat16* uB = g_wuT + (size_t)e * FF * DIM + (size_t)n0 * DIM;

    auto load_stage = [&](int s, int kb) {
        int k0 = kb * BK;
        uint32_t st = sb + s * ST1;
#pragma unroll
        for (int i = 0; i < 2; i++) {
            int idx = tid + i * 512;
            int r = idx >> 3, c = idx & 7;
            uint32_t o = r * 128 + ((c ^ (r & 7)) << 4);
            cp16(st + o, tokp[r] + k0 + c * 8);
            cp16(st + 16384 + o, gB + (size_t)r * DIM + k0 + c * 8);
            cp16(st + 32768 + o, uB + (size_t)r * DIM + k0 + c * 8);
        }
        cp_commit();
    };

    int mat = wid >> 3;          // 0 = gate, 1 = up
    int w   = wid & 7;
    int wm  = w >> 2;            // 0..1
    int wn  = w & 3;             // 0..3
    int grow = ((l >> 3) & 1) * 8 + (l & 7);
    int gk   = l >> 4;
    int rsw  = grow & 7;
    uint32_t rowA[4], rowB[2];
#pragma unroll
    for (int i = 0; i < 4; i++) rowA[i] = (wm * 64 + i * 16 + grow) * 128;
#pragma unroll
    for (int nf = 0; nf < 2; nf++)
        rowB[nf] = 16384 + mat * 16384 + (wn * 32 + nf * 16 + grow) * 128;

    float acc[4][4][4];
#pragma unroll
    for (int i = 0; i < 4; i++)
#pragma unroll
        for (int j = 0; j < 4; j++)
#pragma unroll
            for (int k = 0; k < 4; k++) acc[i][j][k] = 0.f;

    load_stage(0, 0);
    load_stage(1, 1);

    for (int it = 0; it < NIT1; it++) {
        int s = it % 3;
        if (it < NIT1 - 1) cp_wait1(); else cp_wait0();
        __syncthreads();
        if (it + 2 < NIT1) load_stage((it + 2) % 3, it + 2);
        uint32_t st = sb + s * ST1;
#pragma unroll
        for (int kk = 0; kk < 4; kk++) {
            int ck = kk * 2 + gk;
            uint32_t koff = (uint32_t)((ck ^ rsw) << 4);
            uint32_t a[4][4], bb[2][4];
#pragma unroll
            for (int i = 0; i < 4; i++) ldsm4(a[i], st + rowA[i] + koff);
#pragma unroll
            for (int nf = 0; nf < 2; nf++) ldsm4(bb[nf], st + rowB[nf] + koff);
#pragma unroll
            for (int i = 0; i < 4; i++) {
                mma16816(acc[i][0], a[i], bb[0][0], bb[0][2]);
                mma16816(acc[i][1], a[i], bb[0][1], bb[0][3]);
                mma16816(acc[i][2], a[i], bb[1][0], bb[1][2]);
                mma16816(acc[i][3], a[i], bb[1][1], bb[1][3]);
            }
        }
    }
    __syncthreads();

    // epilogue: up warps stage fp32 -> smem; gate warps silu*up -> bf16 smem;
    // all 512 threads stream uint4 stores to gmem.
    float* Cu = (float*)smem;                              // 128 x 136 fp32
    __nv_bfloat16* Hs = (__nv_bfloat16*)(smem + 73728);    // 128 x 136 bf16
    if (mat == 1) {
#pragma unroll
        for (int i = 0; i < 4; i++)
#pragma unroll
            for (int j = 0; j < 4; j++) {
                int r = wm * 64 + i * 16 + (l >> 2);
                int c = wn * 32 + j * 8 + (l & 3) * 2;
                Cu[r * 136 + c]           = acc[i][j][0];
                Cu[r * 136 + c + 1]       = acc[i][j][1];
                Cu[(r + 8) * 136 + c]     = acc[i][j][2];
                Cu[(r + 8) * 136 + c + 1] = acc[i][j][3];
            }
    }
    __syncthreads();
    if (mat == 0) {
#pragma unroll
        for (int i = 0; i < 4; i++)
#pragma unroll
            for (int j = 0; j < 4; j++) {
                int r = wm * 64 + i * 16 + (l >> 2);
                int c = wn * 32 + j * 8 + (l & 3) * 2;
#pragma unroll
                for (int h = 0; h < 2; h++) {
                    int rr = r + h * 8;
                    float g0 = acc[i][j][2 * h], g1 = acc[i][j][2 * h + 1];
                    float u0 = Cu[rr * 136 + c], u1 = Cu[rr * 136 + c + 1];
                    float h0 = g0 / (1.f + __expf(-g0)) * u0;
                    float h1 = g1 / (1.f + __expf(-g1)) * u1;
                    __nv_bfloat162 b2 = __floats2bfloat162_rn(h0, h1);
                    *(uint32_t*)(Hs + rr * 136 + c) = *(uint32_t*)&b2;
                }
            }
    }
    __syncthreads();
#pragma unroll
    for (int k = 0; k < 4; k++) {
        int idx = tid + k * 512;
        int r = idx >> 4, c8 = (idx & 15) * 8;
        if (m0 + r < rows)
            *(uint4*)(g_h + ((size_t)e * CAP + m0 + r) * FF + n0 + c8) =
                *(const uint4*)(Hs + r * 136 + c8);
    }
}

// ---------------- GEMM2: 128x256 CTA, 512 threads, 16 warps of 64x32 ---------
__global__ void __launch_bounds__(512, 1) k_gemm2() {
    extern __shared__ char smem[];
    __shared__ int   stok[128];
    __shared__ float sprob[128];

    int e = blockIdx.x / NBM;
    int m0 = (blockIdx.x % NBM) * 128;
    int rows = g_rows[e];
    if (m0 >= rows) return;
    int n0 = blockIdx.y * 256;
    int tid = threadIdx.x;
    int wid = tid >> 5, l = tid & 31;

    if (tid < 128) {
        int gr = m0 + tid;
        int tok = g_dest[e * CAP + ((gr < rows) ? gr : 0)];
        stok[tid] = tok;
        sprob[tid] = g_topv[tok];
    }
    __syncthreads();

    uint32_t sb = s2u(smem);
    const __nv_bfloat16* Ab = g_h + ((size_t)e * CAP + m0) * FF;
    const __nv_bfloat16* Bb = g_wdT + (size_t)e * DIM * FF + (size_t)n0 * FF;

    auto load_stage = [&](int s, int kb) {
        int k0 = kb * BK;
        uint32_t st = sb + s * ST2;
        // A: 128 rows x 8 chunks = 1024 cp16
#pragma unroll
        for (int i = 0; i < 2; i++) {
            int idx = tid + i * 512;
            int r = idx >> 3, c = idx & 7;
            uint32_t o = r * 128 + ((c ^ (r & 7)) << 4);
            cp16(st + o, Ab + (size_t)r * FF + k0 + c * 8);
        }
        // B: 256 rows x 8 chunks = 2048 cp16
#pragma unroll
        for (int i = 0; i < 4; i++) {
            int idx = tid + i * 512;
            int r = idx >> 3, c = idx & 7;
            uint32_t o = r * 128 + ((c ^ (r & 7)) << 4);
            cp16(st + 16384 + o, Bb + (size_t)r * FF + k0 + c * 8);
        }
        cp_commit();
    };

    int wm = wid >> 3;           // 0..1 -> rows wm*64
    int wn = wid & 7;            // 0..7 -> cols wn*32
    int grow = ((l >> 3) & 1) * 8 + (l & 7);
    int gk   = l >> 4;
    int rsw  = grow & 7;
    uint32_t rowA[4], rowB[2];
#pragma unroll
    for (int i = 0; i < 4; i++) rowA[i] = (wm * 64 + i * 16 + grow) * 128;
#pragma unroll
    for (int nf = 0; nf < 2; nf++)
        rowB[nf] = 16384 + (wn * 32 + nf * 16 + grow) * 128;

    float acc[4][4][4];
#pragma unroll
    for (int i = 0; i < 4; i++)
#pragma unroll
        for (int j = 0; j < 4; j++)
#pragma unroll
            for (int k = 0; k < 4; k++) acc[i][j][k] = 0.f;

    load_stage(0, 0);
    load_stage(1, 1);

    for (int it = 0; it < NIT2; it++) {
        int s = it % 3;
        if (it < NIT2 - 1) cp_wait1(); else cp_wait0();
        __syncthreads();
        if (it + 2 < NIT2) load_stage((it + 2) % 3, it + 2);
        uint32_t st = sb + s * ST2;
#pragma unroll
        for (int kk = 0; kk < 4; kk++) {
            int ck = kk * 2 + gk;
            uint32_t koff = (uint32_t)((ck ^ rsw) << 4);
            uint32_t a[4][4], bb[2][4];
#pragma unroll
            for (int i = 0; i < 4; i++) ldsm4(a[i], st + rowA[i] + koff);
#pragma unroll
            for (int nf = 0; nf < 2; nf++) ldsm4(bb[nf], st + rowB[nf] + koff);
#pragma unroll
            for (int i = 0; i < 4; i++) {
                mma16816(acc[i][0], a[i], bb[0][0], bb[0][2]);
                mma16816(acc[i][1], a[i], bb[0][1], bb[0][3]);
                mma16816(acc[i][2], a[i], bb[1][0], bb[1][2]);
                mma16816(acc[i][3], a[i], bb[1][1], bb[1][3]);
            }
        }
    }
    __syncthreads();

    // stage fp32 result (128 x 264 stride), then coalesced scaled scatter
    float* Cs = (float*)smem;     // 128 x 264 fp32 = 135168 B
#pragma unroll
    for (int i = 0; i < 4; i++)
#pragma unroll
        for (int j = 0; j < 4; j++) {
            int r = wm * 64 + i * 16 + (l >> 2);
            int c = wn * 32 + j * 8 + (l & 3) * 2;
            Cs[r * 264 + c]           = acc[i][j][0];
            Cs[r * 264 + c + 1]       = acc[i][j][1];
            Cs[(r + 8) * 264 + c]     = acc[i][j][2];
            Cs[(r + 8) * 264 + c + 1] = acc[i][j][3];
        }
    __syncthreads();

#pragma unroll
    for (int k = 0; k < 16; k++) {
        int idx = tid + k * 512;
        int r = idx >> 6, cc = (idx & 63) * 4;
        if (m0 + r < rows) {
            int tok = stok[r];
            float p = sprob[r];
            float4 v;
            v.x = Cs[r * 264 + cc]     * p;
            v.y = Cs[r * 264 + cc + 1] * p;
            v.z = Cs[r * 264 + cc + 2] * p;
            v.w = Cs[r * 264 + cc + 3] * p;
            *(float4*)(g_ffn + (size_t)tok * DIM + n0 + cc) = v;
        }
    }
}

// ---------------- residual + LayerNorm (+ lb loss from block 0) ---------------
__global__ void __launch_bounds__(256) k_ln(const float* __restrict__ x,
                                            const float* __restrict__ lng,
                                            const float* __restrict__ lnb,
                                            float* __restrict__ out, int out_size) {
    int t = blockIdx.x, tid = threadIdx.x;
    if (t == 0 && tid == 0) {
        float lb = 0.f;
        const float invN = 1.f / (float)NTOK;
#pragma unroll
        for (int e = 0; e < NE; e++)
            lb += ((float)g_cnt[e] * invN) * (g_sumP[e] * invN);
        lb *= (float)NE;
        if (out_size > NTOK * DIM) out[NTOK * DIM] = lb;
    }
    const float* xr = x + (size_t)t * DIM;
    const float* fr = g_ffn + (size_t)t * DIM;
    float v[4], s = 0.f, s2 = 0.f;
#pragma unroll
    for (int i = 0; i < 4; i++) {
        int c = tid + i * 256;
        float r = xr[c] + fr[c];
        v[i] = r; s += r; s2 += r * r;
    }
#pragma unroll
    for (int o = 16; o; o >>= 1) {
        s  += __shfl_xor_sync(0xffffffffu, s, o);
        s2 += __shfl_xor_sync(0xffffffffu, s2, o);
    }
    __shared__ float sh[16];
    int w = tid >> 5;
    if ((tid & 31) == 0) { sh[w] = s; sh[8 + w] = s2; }
    __syncthreads();
    float S = 0.f, S2 = 0.f;
#pragma unroll
    for (int i = 0; i < 8; i++) { S += sh[i]; S2 += sh[8 + i]; }
    float mu = S * (1.f / DIM);
    float var = S2 * (1.f / DIM) - mu * mu;
    float inv = rsqrtf(var + 1e-5f);
    float* orow = out + (size_t)t * DIM;
#pragma unroll
    for (int i = 0; i < 4; i++) {
        int c = tid + i * 256;
        orow[c] = (v[i] - mu) * inv * lng[c] + lnb[c];
    }
}

// ---------------- launch --------------------------------------------------------
extern "C" void kernel_launch(void* const* d_in, const int* in_sizes, int n_in,
                              void* d_out, int out_size) {
    const float* x   = (const float*)d_in[0];
    const float* rw  = (const float*)d_in[1];
    const float* gw  = (const float*)d_in[2];
    const float* uw  = (const float*)d_in[3];
    const float* dw  = (const float*)d_in[4];
    const float* lng = (const float*)d_in[5];
    const float* lnb = (const float*)d_in[6];
    float* out = (float*)d_out;
    (void)in_sizes; (void)n_in;

    static bool init_done = false;
    static cudaStream_t s1, s2, s3;
    static cudaEvent_t evFork, evJoin1, evJoin2, evJoin3;
    if (!init_done) {
        cudaFuncSetAttribute(k_gemm1, cudaFuncAttributeMaxDynamicSharedMemorySize, 3 * ST1);
        cudaFuncSetAttribute(k_gemm2, cudaFuncAttributeMaxDynamicSharedMemorySize, 3 * ST2);
        cudaStreamCreateWithFlags(&s1, cudaStreamNonBlocking);
        cudaStreamCreateWithFlags(&s2, cudaStreamNonBlocking);
        cudaStreamCreateWithFlags(&s3, cudaStreamNonBlocking);
        cudaEventCreateWithFlags(&evFork, cudaEventDisableTiming);
        cudaEventCreateWithFlags(&evJoin1, cudaEventDisableTiming);
        cudaEventCreateWithFlags(&evJoin2, cudaEventDisableTiming);
        cudaEventCreateWithFlags(&evJoin3, cudaEventDisableTiming);
        init_done = true;
    }

    __nv_bfloat16* wgT; cudaGetSymbolAddress((void**)&wgT, g_wgT);
    __nv_bfloat16* wuT; cudaGetSymbolAddress((void**)&wuT, g_wuT);
    __nv_bfloat16* wdT; cudaGetSymbolAddress((void**)&wdT, g_wdT);

    // anchor on default stream (capture origin), then fork to 3 side streams
    k_anchor<<<1, 32>>>();
    cudaEventRecord(evFork, 0);
    cudaStreamWaitEvent(s1, evFork, 0);
    cudaStreamWaitEvent(s2, evFork, 0);
    cudaStreamWaitEvent(s3, evFork, 0);

    k_transpose<<<dim3(FF / 32, DIM / 32, NE), 256, 0, s1>>>(gw, wgT, DIM, FF);
    cudaEventRecord(evJoin1, s1);
    k_transpose<<<dim3(FF / 32, DIM / 32, NE), 256, 0, s2>>>(uw, wuT, DIM, FF);
    cudaEventRecord(evJoin2, s2);
    k_transpose<<<dim3(DIM / 32, FF / 32, NE), 256, 0, s3>>>(dw, wdT, FF, DIM);
    cudaEventRecord(evJoin3, s3);

    // token-side pipeline on default stream
    k_router<<<NRB, 256>>>(x, rw);
    k_scan<<<1, 256>>>();

    cudaStreamWaitEvent(0, evJoin1, 0);
    cudaStreamWaitEvent(0, evJoin2, 0);
    cudaStreamWaitEvent(0, evJoin3, 0);

    k_gemm1<<<dim3(NE * NBM, FF / 128), 512, 3 * ST1>>>();
    k_gemm2<<<dim3(NE * NBM, DIM / 256), 512, 3 * ST2>>>();

    k_ln<<<NTOK, 256>>>(x, lng, lnb, out, out_size);
}

// round 15
// speedup vs baseline: 1.0515x; 1.0515x over previous
#include <cuda_runtime.h>
#include <cuda_bf16.h>
#include <cstdint>

#define NTOK 16384
#define DIM  1024
#define FF   4096
#define NE   8
#define CAP  2560
#define NBM  20            // CAP / 128
#define BK   64
#define NIT1 (DIM / BK)    // 16
#define NIT2 (FF / BK)     // 64
#define ST1  49152         // stage bytes gemm1: A 16K + Bg 16K + Bu 16K
#define ST2  32768         // stage bytes gemm2: A 16K + B 16K
#define NRB  (NTOK / 8)    // router blocks = 2048

// ---------------- scratch globals -------------------------------------------
__device__ __nv_bfloat16 g_xb[(size_t)NTOK * DIM];
__device__ __nv_bfloat16 g_wgT[(size_t)NE * FF * DIM];  // [E][F][D]
__device__ __nv_bfloat16 g_wuT[(size_t)NE * FF * DIM];  // [E][F][D]
__device__ __nv_bfloat16 g_wdT[(size_t)NE * DIM * FF];  // [E][D][F]
__device__ __nv_bfloat16 g_h[(size_t)NE * CAP * FF];
__device__ float g_ffn[(size_t)NTOK * DIM];
__device__ int   g_top1[NTOK];
__device__ float g_topv[NTOK];
__device__ int   g_dest[NE * CAP];
__device__ int   g_rows[NE];
__device__ int   g_cnt[NE];
__device__ float g_sumP[NE];
__device__ float g_blockP[NRB][NE];

// ---------------- PTX helpers ------------------------------------------------
__device__ __forceinline__ uint32_t s2u(const void* p) {
    return (uint32_t)__cvta_generic_to_shared(p);
}
__device__ __forceinline__ void cp16(uint32_t dst, const void* src) {
    asm volatile("cp.async.cg.shared.global [%0], [%1], 16;\n" :: "r"(dst), "l"(src));
}
__device__ __forceinline__ void cp_commit() { asm volatile("cp.async.commit_group;\n" ::: "memory"); }
__device__ __forceinline__ void cp_wait0()  { asm volatile("cp.async.wait_group 0;\n" ::: "memory"); }
__device__ __forceinline__ void cp_wait1()  { asm volatile("cp.async.wait_group 1;\n" ::: "memory"); }

__device__ __forceinline__ void ldsm4(uint32_t (&d)[4], uint32_t addr) {
    asm volatile("ldmatrix.sync.aligned.m8n8.x4.shared.b16 {%0,%1,%2,%3}, [%4];"
        : "=r"(d[0]), "=r"(d[1]), "=r"(d[2]), "=r"(d[3]) : "r"(addr));
}
__device__ __forceinline__ void mma16816(float (&c)[4], const uint32_t (&a)[4],
                                         uint32_t b0, uint32_t b1) {
    asm volatile("mma.sync.aligned.m16n8k16.row.col.f32.bf16.bf16.f32 "
        "{%0,%1,%2,%3}, {%4,%5,%6,%7}, {%8,%9}, {%0,%1,%2,%3};"
        : "+f"(c[0]), "+f"(c[1]), "+f"(c[2]), "+f"(c[3])
        : "r"(a[0]), "r"(a[1]), "r"(a[2]), "r"(a[3]), "r"(b0), "r"(b1));
}

// ---------------- anchor (capture origin) ------------------------------------
__global__ void k_anchor() {}

// ---------------- transpose: fp32 [E][R][C] -> bf16 [E][C][R] ------------------
__global__ void __launch_bounds__(256) k_transpose(const float* __restrict__ in,
                                                   __nv_bfloat16* __restrict__ out,
                                                   int R, int C) {
    __shared__ float tile[32][33];
    int e = blockIdx.z;
    int c0 = blockIdx.x * 32, r0 = blockIdx.y * 32;
    int tx = threadIdx.x & 31, ty = threadIdx.x >> 5;
    const float* src = in + (size_t)e * R * C;
    __nv_bfloat16* dst = out + (size_t)e * C * R;
#pragma unroll
    for (int k = 0; k < 4; k++)
        tile[ty + 8 * k][tx] = src[(size_t)(r0 + ty + 8 * k) * C + c0 + tx];
    __syncthreads();
#pragma unroll
    for (int k = 0; k < 4; k++)
        dst[(size_t)(c0 + ty + 8 * k) * R + r0 + tx] = __float2bfloat16(tile[tx][ty + 8 * k]);
}

// ---------------- router (converts x -> bf16, zeroes g_ffn rows) --------------
__global__ void __launch_bounds__(256) k_router(const float* __restrict__ x,
                                                const float* __restrict__ rw) {
    __shared__ float rwsT[NE][DIM];    // transposed: conflict-free float4 reads
    __shared__ float blockP[NE];
    int tid = threadIdx.x;
    for (int i = tid; i < DIM * NE; i += 256) {
        int d = i >> 3, e = i & 7;
        rwsT[e][d] = rw[i];
    }
    if (tid < NE) blockP[tid] = 0.f;
    __syncthreads();

    int warp = tid >> 5, lane = tid & 31;
    int token = blockIdx.x * 8 + warp;

    float acc[NE];
#pragma unroll
    for (int e = 0; e < NE; e++) acc[e] = 0.f;
    const float* xr = x + (size_t)token * DIM;
    __nv_bfloat16* xb = g_xb + (size_t)token * DIM;
    float* fz = g_ffn + (size_t)token * DIM;
    float4 z4 = make_float4(0.f, 0.f, 0.f, 0.f);
    for (int i = lane * 4; i < DIM; i += 128) {
        float4 v = *(const float4*)(xr + i);
        *(__nv_bfloat162*)(xb + i)     = __floats2bfloat162_rn(v.x, v.y);
        *(__nv_bfloat162*)(xb + i + 2) = __floats2bfloat162_rn(v.z, v.w);
        *(float4*)(fz + i) = z4;
#pragma unroll
        for (int e = 0; e < NE; e++) {
            float4 w = *(const float4*)(&rwsT[e][i]);
            acc[e] += v.x * w.x + v.y * w.y + v.z * w.z + v.w * w.w;
        }
    }
#pragma unroll
    for (int e = 0; e < NE; e++)
#pragma unroll
        for (int o = 16; o; o >>= 1) acc[e] += __shfl_xor_sync(0xffffffffu, acc[e], o);

    if (lane == 0) {
        float m = acc[0]; int am = 0;
#pragma unroll
        for (int e = 1; e < NE; e++) if (acc[e] > m) { m = acc[e]; am = e; }
        float p[NE], s = 0.f;
#pragma unroll
        for (int e = 0; e < NE; e++) { p[e] = __expf(acc[e] - m); s += p[e]; }
        float inv = 1.f / s;
        g_top1[token] = am;
        g_topv[token] = p[am] * inv;
#pragma unroll
        for (int e = 0; e < NE; e++) atomicAdd(&blockP[e], p[e] * inv);
    }
    __syncthreads();
    if (tid < NE) g_blockP[blockIdx.x][tid] = blockP[tid];
}

// ---------------- deterministic scan + prob-sum reduction --------------------
__global__ void k_scan() {
    __shared__ int base[NE];
    __shared__ int wcnt[8][NE];
    int tid = threadIdx.x;
    int warp = tid >> 5, lane = tid & 31;
    unsigned ltmask = (1u << lane) - 1u;

    if (warp < NE) {
        float s = 0.f;
        for (int b = lane; b < NRB; b += 32) s += g_blockP[b][warp];
#pragma unroll
        for (int o = 16; o; o >>= 1) s += __shfl_xor_sync(0xffffffffu, s, o);
        if (lane == 0) g_sumP[warp] = s;
    }

    if (tid < NE) base[tid] = 0;
    __syncthreads();
    for (int w = 0; w < NTOK / 256; w++) {
        int t = w * 256 + tid;
        int e = g_top1[t];
        int myrank = 0;
#pragma unroll
        for (int ee = 0; ee < NE; ee++) {
            unsigned b = __ballot_sync(0xffffffffu, e == ee);
            if (lane == ee) wcnt[warp][ee] = __popc(b);
            if (e == ee) myrank = __popc(b & ltmask);
        }
        __syncthreads();
        int off = base[e];
        for (int w2 = 0; w2 < warp; w2++) off += wcnt[w2][e];
        int p = off + myrank;
        if (p < CAP) g_dest[e * CAP + p] = t;
        __syncthreads();
        if (tid < NE) {
            int s = 0;
#pragma unroll
            for (int w2 = 0; w2 < 8; w2++) s += wcnt[w2][tid];
            base[tid] += s;
        }
        __syncthreads();
    }
    if (tid < NE) {
        g_cnt[tid] = base[tid];
        g_rows[tid] = min(base[tid], CAP);
    }
}

// ---------------- GEMM1: mma.sync, h = silu(X Wg) * (X Wu) -------------------
// CTA: M=128 x N=128 (both), 512 threads; warps 0-7 gate, 8-15 up; 64x32 tiles
__global__ void __launch_bounds__(512, 1) k_gemm1() {
    extern __shared__ char smem[];
    __shared__ const __nv_bfloat16* tokp[128];

    int e = blockIdx.x / NBM;
    int m0 = (blockIdx.x % NBM) * 128;
    int rows = g_rows[e];
    if (m0 >= rows) return;
    int n0 = blockIdx.y * 128;
    int tid = threadIdx.x;
    int wid = tid >> 5, l = tid & 31;

    if (tid < 128) {
        int gr = m0 + tid;
        tokp[tid] = g_xb + (size_t)g_dest[e * CAP + ((gr < rows) ? gr : 0)] * DIM;
    }
    __syncthreads();

    uint32_t sb = s2u(smem);
    const __nv_bfloat16* gB = g_wgT + (size_t)e * FF * DIM + (size_t)n0 * DIM;
    const __nv_bfloat16* uB = g_wuT + (size_t)e * FF * DIM + (size_t)n0 * DIM;

    auto load_stage = [&](int s, int kb) {
        int k0 = kb * BK;
        uint32_t st = sb + s * ST1;
#pragma unroll
        for (int i = 0; i < 2; i++) {
            int idx = tid + i * 512;
            int r = idx >> 3, c = idx & 7;
            uint32_t o = r * 128 + ((c ^ (r & 7)) << 4);
            cp16(st + o, tokp[r] + k0 + c * 8);
            cp16(st + 16384 + o, gB + (size_t)r * DIM + k0 + c * 8);
            cp16(st + 32768 + o, uB + (size_t)r * DIM + k0 + c * 8);
        }
        cp_commit();
    };

    int mat = wid >> 3;          // 0 = gate, 1 = up
    int w   = wid & 7;
    int wm  = w >> 2;            // 0..1
    int wn  = w & 3;             // 0..3
    int grow = ((l >> 3) & 1) * 8 + (l & 7);
    int gk   = l >> 4;
    int rsw  = grow & 7;
    uint32_t rowA[4], rowB[2];
#pragma unroll
    for (int i = 0; i < 4; i++) rowA[i] = (wm * 64 + i * 16 + grow) * 128;
#pragma unroll
    for (int nf = 0; nf < 2; nf++)
        rowB[nf] = 16384 + mat * 16384 + (wn * 32 + nf * 16 + grow) * 128;

    float acc[4][4][4];
#pragma unroll
    for (int i = 0; i < 4; i++)
#pragma unroll
        for (int j = 0; j < 4; j++)
#pragma unroll
            for (int k = 0; k < 4; k++) acc[i][j][k] = 0.f;

    load_stage(0, 0);
    load_stage(1, 1);

    for (int it = 0; it < NIT1; it++) {
        int s = it % 3;
        if (it < NIT1 - 1) cp_wait1(); else cp_wait0();
        __syncthreads();
        if (it + 2 < NIT1) load_stage((it + 2) % 3, it + 2);
        uint32_t st = sb + s * ST1;
#pragma unroll
        for (int kk = 0; kk < 4; kk++) {
            int ck = kk * 2 + gk;
            uint32_t koff = (uint32_t)((ck ^ rsw) << 4);
            uint32_t a[4][4], bb[2][4];
#pragma unroll
            for (int i = 0; i < 4; i++) ldsm4(a[i], st + rowA[i] + koff);
#pragma unroll
            for (int nf = 0; nf < 2; nf++) ldsm4(bb[nf], st + rowB[nf] + koff);
#pragma unroll
            for (int i = 0; i < 4; i++) {
                mma16816(acc[i][0], a[i], bb[0][0], bb[0][2]);
                mma16816(acc[i][1], a[i], bb[0][1], bb[0][3]);
                mma16816(acc[i][2], a[i], bb[1][0], bb[1][2]);
                mma16816(acc[i][3], a[i], bb[1][1], bb[1][3]);
            }
        }
    }
    __syncthreads();

    // epilogue: up warps stage fp32 -> smem; gate warps silu*up -> bf16 smem;
    // all 512 threads stream uint4 stores to gmem.
    float* Cu = (float*)smem;                              // 128 x 136 fp32
    __nv_bfloat16* Hs = (__nv_bfloat16*)(smem + 73728);    // 128 x 136 bf16
    if (mat == 1) {
#pragma unroll
        for (int i = 0; i < 4; i++)
#pragma unroll
            for (int j = 0; j < 4; j++) {
                int r = wm * 64 + i * 16 + (l >> 2);
                int c = wn * 32 + j * 8 + (l & 3) * 2;
                Cu[r * 136 + c]           = acc[i][j][0];
                Cu[r * 136 + c + 1]       = acc[i][j][1];
                Cu[(r + 8) * 136 + c]     = acc[i][j][2];
                Cu[(r + 8) * 136 + c + 1] = acc[i][j][3];
            }
    }
    __syncthreads();
    if (mat == 0) {
#pragma unroll
        for (int i = 0; i < 4; i++)
#pragma unroll
            for (int j = 0; j < 4; j++) {
                int r = wm * 64 + i * 16 + (l >> 2);
                int c = wn * 32 + j * 8 + (l & 3) * 2;
#pragma unroll
                for (int h = 0; h < 2; h++) {
                    int rr = r + h * 8;
                    float g0 = acc[i][j][2 * h], g1 = acc[i][j][2 * h + 1];
                    float u0 = Cu[rr * 136 + c], u1 = Cu[rr * 136 + c + 1];
                    float h0 = g0 / (1.f + __expf(-g0)) * u0;
                    float h1 = g1 / (1.f + __expf(-g1)) * u1;
                    __nv_bfloat162 b2 = __floats2bfloat162_rn(h0, h1);
                    *(uint32_t*)(Hs + rr * 136 + c) = *(uint32_t*)&b2;
                }
            }
    }
    __syncthreads();
#pragma unroll
    for (int k = 0; k < 4; k++) {
        int idx = tid + k * 512;
        int r = idx >> 4, c8 = (idx & 15) * 8;
        if (m0 + r < rows)
            *(uint4*)(g_h + ((size_t)e * CAP + m0 + r) * FF + n0 + c8) =
                *(const uint4*)(Hs + r * 136 + c8);
    }
}

// ---------------- GEMM2: mma.sync, y = H Wd, scaled scatter -------------------
// CTA: M=128 x N=128, 256 threads, occupancy 2; warps 2m x 4n of 64x32
// grid: x = n-block (8), y = expert*m-tile (160)  -> consecutive CTAs share A
__global__ void __launch_bounds__(256, 2) k_gemm2() {
    extern __shared__ char smem[];
    __shared__ int   stok[128];
    __shared__ float sprob[128];

    int e = blockIdx.y / NBM;
    int m0 = (blockIdx.y % NBM) * 128;
    int rows = g_rows[e];
    if (m0 >= rows) return;
    int n0 = blockIdx.x * 128;
    int tid = threadIdx.x;
    int wid = tid >> 5, l = tid & 31;

    if (tid < 128) {
        int gr = m0 + tid;
        int tok = g_dest[e * CAP + ((gr < rows) ? gr : 0)];
        stok[tid] = tok;
        sprob[tid] = g_topv[tok];
    }
    __syncthreads();

    uint32_t sb = s2u(smem);
    const __nv_bfloat16* Ab = g_h + ((size_t)e * CAP + m0) * FF;
    const __nv_bfloat16* Bb = g_wdT + (size_t)e * DIM * FF + (size_t)n0 * FF;

    auto load_stage = [&](int s, int kb) {
        int k0 = kb * BK;
        uint32_t st = sb + s * ST2;
#pragma unroll
        for (int i = 0; i < 4; i++) {
            int idx = tid + i * 256;
            int r = idx >> 3, c = idx & 7;
            uint32_t o = r * 128 + ((c ^ (r & 7)) << 4);
            cp16(st + o, Ab + (size_t)r * FF + k0 + c * 8);
            cp16(st + 16384 + o, Bb + (size_t)r * FF + k0 + c * 8);
        }
        cp_commit();
    };

    int wm = wid >> 2;           // 0..1
    int wn = wid & 3;            // 0..3
    int grow = ((l >> 3) & 1) * 8 + (l & 7);
    int gk   = l >> 4;
    int rsw  = grow & 7;
    uint32_t rowA[4], rowB[2];
#pragma unroll
    for (int i = 0; i < 4; i++) rowA[i] = (wm * 64 + i * 16 + grow) * 128;
#pragma unroll
    for (int nf = 0; nf < 2; nf++)
        rowB[nf] = 16384 + (wn * 32 + nf * 16 + grow) * 128;

    float acc[4][4][4];
#pragma unroll
    for (int i = 0; i < 4; i++)
#pragma unroll
        for (int j = 0; j < 4; j++)
#pragma unroll
            for (int k = 0; k < 4; k++) acc[i][j][k] = 0.f;

    load_stage(0, 0);
    load_stage(1, 1);

    for (int it = 0; it < NIT2; it++) {
        int s = it % 3;
        if (it < NIT2 - 1) cp_wait1(); else cp_wait0();
        __syncthreads();
        if (it + 2 < NIT2) load_stage((it + 2) % 3, it + 2);
        uint32_t st = sb + s * ST2;
#pragma unroll
        for (int kk = 0; kk < 4; kk++) {
            int ck = kk * 2 + gk;
            uint32_t koff = (uint32_t)((ck ^ rsw) << 4);
            uint32_t a[4][4], bb[2][4];
#pragma unroll
            for (int i = 0; i < 4; i++) ldsm4(a[i], st + rowA[i] + koff);
#pragma unroll
            for (int nf = 0; nf < 2; nf++) ldsm4(bb[nf], st + rowB[nf] + koff);
#pragma unroll
            for (int i = 0; i < 4; i++) {
                mma16816(acc[i][0], a[i], bb[0][0], bb[0][2]);
                mma16816(acc[i][1], a[i], bb[0][1], bb[0][3]);
                mma16816(acc[i][2], a[i], bb[1][0], bb[1][2]);
                mma16816(acc[i][3], a[i], bb[1][1], bb[1][3]);
            }
        }
    }
    __syncthreads();

    // stage fp32 result, then coalesced scaled scatter
    float* Cs = (float*)smem;     // 128 x 136 fp32
#pragma unroll
    for (int i = 0; i < 4; i++)
#pragma unroll
        for (int j = 0; j < 4; j++) {
            int r = wm * 64 + i * 16 + (l >> 2);
            int c = wn * 32 + j * 8 + (l & 3) * 2;
            Cs[r * 136 + c]           = acc[i][j][0];
            Cs[r * 136 + c + 1]       = acc[i][j][1];
            Cs[(r + 8) * 136 + c]     = acc[i][j][2];
            Cs[(r + 8) * 136 + c + 1] = acc[i][j][3];
        }
    __syncthreads();

#pragma unroll
    for (int k = 0; k < 16; k++) {
        int idx = tid + k * 256;
        int r = idx >> 5, cc = (idx & 31) * 4;
        if (m0 + r < rows) {
            int tok = stok[r];
            float p = sprob[r];
            float4 v;
            v.x = Cs[r * 136 + cc]     * p;
            v.y = Cs[r * 136 + cc + 1] * p;
            v.z = Cs[r * 136 + cc + 2] * p;
            v.w = Cs[r * 136 + cc + 3] * p;
            *(float4*)(g_ffn + (size_t)tok * DIM + n0 + cc) = v;
        }
    }
}

// ---------------- residual + LayerNorm (+ lb loss from block 0) ---------------
__global__ void __launch_bounds__(256) k_ln(const float* __restrict__ x,
                                            const float* __restrict__ lng,
                                            const float* __restrict__ lnb,
                                            float* __restrict__ out, int out_size) {
    int t = blockIdx.x, tid = threadIdx.x;
    if (t == 0 && tid == 0) {
        float lb = 0.f;
        const float invN = 1.f / (float)NTOK;
#pragma unroll
        for (int e = 0; e < NE; e++)
            lb += ((float)g_cnt[e] * invN) * (g_sumP[e] * invN);
        lb *= (float)NE;
        if (out_size > NTOK * DIM) out[NTOK * DIM] = lb;
    }
    const float* xr = x + (size_t)t * DIM;
    const float* fr = g_ffn + (size_t)t * DIM;
    float v[4], s = 0.f, s2 = 0.f;
#pragma unroll
    for (int i = 0; i < 4; i++) {
        int c = tid + i * 256;
        float r = xr[c] + fr[c];
        v[i] = r; s += r; s2 += r * r;
    }
#pragma unroll
    for (int o = 16; o; o >>= 1) {
        s  += __shfl_xor_sync(0xffffffffu, s, o);
        s2 += __shfl_xor_sync(0xffffffffu, s2, o);
    }
    __shared__ float sh[16];
    int w = tid >> 5;
    if ((tid & 31) == 0) { sh[w] = s; sh[8 + w] = s2; }
    __syncthreads();
    float S = 0.f, S2 = 0.f;
#pragma unroll
    for (int i = 0; i < 8; i++) { S += sh[i]; S2 += sh[8 + i]; }
    float mu = S * (1.f / DIM);
    float var = S2 * (1.f / DIM) - mu * mu;
    float inv = rsqrtf(var + 1e-5f);
    float* orow = out + (size_t)t * DIM;
#pragma unroll
    for (int i = 0; i < 4; i++) {
        int c = tid + i * 256;
        orow[c] = (v[i] - mu) * inv * lng[c] + lnb[c];
    }
}

// ---------------- launch --------------------------------------------------------
extern "C" void kernel_launch(void* const* d_in, const int* in_sizes, int n_in,
                              void* d_out, int out_size) {
    const float* x   = (const float*)d_in[0];
    const float* rw  = (const float*)d_in[1];
    const float* gw  = (const float*)d_in[2];
    const float* uw  = (const float*)d_in[3];
    const float* dw  = (const float*)d_in[4];
    const float* lng = (const float*)d_in[5];
    const float* lnb = (const float*)d_in[6];
    float* out = (float*)d_out;
    (void)in_sizes; (void)n_in;

    static bool init_done = false;
    static cudaStream_t s1, s2, s3;
    static cudaEvent_t evFork, evJoin1, evJoin2, evJoin3;
    if (!init_done) {
        cudaFuncSetAttribute(k_gemm1, cudaFuncAttributeMaxDynamicSharedMemorySize, 3 * ST1);
        cudaFuncSetAttribute(k_gemm2, cudaFuncAttributeMaxDynamicSharedMemorySize, 3 * ST2);
        cudaStreamCreateWithFlags(&s1, cudaStreamNonBlocking);
        cudaStreamCreateWithFlags(&s2, cudaStreamNonBlocking);
        cudaStreamCreateWithFlags(&s3, cudaStreamNonBlocking);
        cudaEventCreateWithFlags(&evFork, cudaEventDisableTiming);
        cudaEventCreateWithFlags(&evJoin1, cudaEventDisableTiming);
        cudaEventCreateWithFlags(&evJoin2, cudaEventDisableTiming);
        cudaEventCreateWithFlags(&evJoin3, cudaEventDisableTiming);
        init_done = true;
    }

    __nv_bfloat16* wgT; cudaGetSymbolAddress((void**)&wgT, g_wgT);
    __nv_bfloat16* wuT; cudaGetSymbolAddress((void**)&wuT, g_wuT);
    __nv_bfloat16* wdT; cudaGetSymbolAddress((void**)&wdT, g_wdT);

    // anchor on default stream (capture origin), then fork to 3 side streams
    k_anchor<<<1, 32>>>();
    cudaEventRecord(evFork, 0);
    cudaStreamWaitEvent(s1, evFork, 0);
    cudaStreamWaitEvent(s2, evFork, 0);
    cudaStreamWaitEvent(s3, evFork, 0);

    k_transpose<<<dim3(FF / 32, DIM / 32, NE), 256, 0, s1>>>(gw, wgT, DIM, FF);
    cudaEventRecord(evJoin1, s1);
    k_transpose<<<dim3(FF / 32, DIM / 32, NE), 256, 0, s2>>>(uw, wuT, DIM, FF);
    cudaEventRecord(evJoin2, s2);
    k_transpose<<<dim3(DIM / 32, FF / 32, NE), 256, 0, s3>>>(dw, wdT, FF, DIM);
    cudaEventRecord(evJoin3, s3);

    // token-side pipeline on default stream
    k_router<<<NRB, 256>>>(x, rw);
    k_scan<<<1, 256>>>();

    cudaStreamWaitEvent(0, evJoin1, 0);
    cudaStreamWaitEvent(0, evJoin2, 0);
    cudaStreamWaitEvent(0, evJoin3, 0);

    k_gemm1<<<dim3(NE * NBM, FF / 128), 512, 3 * ST1>>>();
    k_gemm2<<<dim3(DIM / 128, NE * NBM), 256, 3 * ST2>>>();

    k_ln<<<NTOK, 256>>>(x, lng, lnb, out, out_size);
}

// round 16
// speedup vs baseline: 1.0690x; 1.0167x over previous
#include <cuda_runtime.h>
#include <cuda_bf16.h>
#include <cstdint>

#define NTOK 16384
#define DIM  1024
#define FF   4096
#define NE   8
#define CAP  2560
#define NBM  20            // CAP / 128
#define BK   64
#define NIT1 (DIM / BK)    // 16
#define NIT2 (FF / BK)     // 64
#define ST1  49152         // stage bytes gemm1: A 16K + Bg 16K + Bu 16K
#define ST2  32768         // stage bytes gemm2: A 16K + B 16K
#define NRB  (NTOK / 8)    // router blocks = 2048

// ---------------- scratch globals -------------------------------------------
__device__ __nv_bfloat16 g_xb[(size_t)NTOK * DIM];
__device__ __nv_bfloat16 g_wgT[(size_t)NE * FF * DIM];  // [E][F][D]
__device__ __nv_bfloat16 g_wuT[(size_t)NE * FF * DIM];  // [E][F][D]
__device__ __nv_bfloat16 g_wdT[(size_t)NE * DIM * FF];  // [E][D][F]
__device__ __nv_bfloat16 g_h[(size_t)NE * CAP * FF];
__device__ float g_y[(size_t)NE * CAP * DIM];           // expert-order FFN output
__device__ int   g_top1[NTOK];
__device__ int   g_pos[NTOK];
__device__ float g_topv[NTOK];
__device__ int   g_dest[NE * CAP];
__device__ int   g_rows[NE];
__device__ int   g_cnt[NE];
__device__ float g_sumP[NE];
__device__ float g_blockP[NRB][NE];

// ---------------- PTX helpers ------------------------------------------------
__device__ __forceinline__ uint32_t s2u(const void* p) {
    return (uint32_t)__cvta_generic_to_shared(p);
}
__device__ __forceinline__ void cp16(uint32_t dst, const void* src) {
    asm volatile("cp.async.cg.shared.global [%0], [%1], 16;\n" :: "r"(dst), "l"(src));
}
__device__ __forceinline__ void cp_commit() { asm volatile("cp.async.commit_group;\n" ::: "memory"); }
__device__ __forceinline__ void cp_wait0()  { asm volatile("cp.async.wait_group 0;\n" ::: "memory"); }
__device__ __forceinline__ void cp_wait1()  { asm volatile("cp.async.wait_group 1;\n" ::: "memory"); }

__device__ __forceinline__ void ldsm4(uint32_t (&d)[4], uint32_t addr) {
    asm volatile("ldmatrix.sync.aligned.m8n8.x4.shared.b16 {%0,%1,%2,%3}, [%4];"
        : "=r"(d[0]), "=r"(d[1]), "=r"(d[2]), "=r"(d[3]) : "r"(addr));
}
__device__ __forceinline__ void mma16816(float (&c)[4], const uint32_t (&a)[4],
                                         uint32_t b0, uint32_t b1) {
    asm volatile("mma.sync.aligned.m16n8k16.row.col.f32.bf16.bf16.f32 "
        "{%0,%1,%2,%3}, {%4,%5,%6,%7}, {%8,%9}, {%0,%1,%2,%3};"
        : "+f"(c[0]), "+f"(c[1]), "+f"(c[2]), "+f"(c[3])
        : "r"(a[0]), "r"(a[1]), "r"(a[2]), "r"(a[3]), "r"(b0), "r"(b1));
}

// ---------------- anchor (capture origin) ------------------------------------
__global__ void k_anchor() {}

// ---------------- transpose: fp32 [E][R][C] -> bf16 [E][C][R], 2 r-tiles ------
__global__ void __launch_bounds__(256) k_transpose(const float* __restrict__ in,
                                                   __nv_bfloat16* __restrict__ out,
                                                   int R, int C) {
    __shared__ float tile[32][33];
    int e = blockIdx.z;
    int c0 = blockIdx.x * 32;
    int tx = threadIdx.x & 31, ty = threadIdx.x >> 5;
    const float* src = in + (size_t)e * R * C;
    __nv_bfloat16* dst = out + (size_t)e * C * R;
#pragma unroll
    for (int h = 0; h < 2; h++) {
        int r0 = (blockIdx.y * 2 + h) * 32;
#pragma unroll
        for (int k = 0; k < 4; k++)
            tile[ty + 8 * k][tx] = src[(size_t)(r0 + ty + 8 * k) * C + c0 + tx];
        __syncthreads();
#pragma unroll
        for (int k = 0; k < 4; k++)
            dst[(size_t)(c0 + ty + 8 * k) * R + r0 + tx] = __float2bfloat16(tile[tx][ty + 8 * k]);
        __syncthreads();
    }
}

// ---------------- router (converts x -> bf16) ---------------------------------
__global__ void __launch_bounds__(256) k_router(const float* __restrict__ x,
                                                const float* __restrict__ rw) {
    __shared__ float rwsT[NE][DIM];    // transposed: conflict-free float4 reads
    __shared__ float blockP[NE];
    int tid = threadIdx.x;
    for (int i = tid; i < DIM * NE; i += 256) {
        int d = i >> 3, e = i & 7;
        rwsT[e][d] = rw[i];
    }
    if (tid < NE) blockP[tid] = 0.f;
    __syncthreads();

    int warp = tid >> 5, lane = tid & 31;
    int token = blockIdx.x * 8 + warp;

    float acc[NE];
#pragma unroll
    for (int e = 0; e < NE; e++) acc[e] = 0.f;
    const float* xr = x + (size_t)token * DIM;
    __nv_bfloat16* xb = g_xb + (size_t)token * DIM;
    for (int i = lane * 4; i < DIM; i += 128) {
        float4 v = *(const float4*)(xr + i);
        *(__nv_bfloat162*)(xb + i)     = __floats2bfloat162_rn(v.x, v.y);
        *(__nv_bfloat162*)(xb + i + 2) = __floats2bfloat162_rn(v.z, v.w);
#pragma unroll
        for (int e = 0; e < NE; e++) {
            float4 w = *(const float4*)(&rwsT[e][i]);
            acc[e] += v.x * w.x + v.y * w.y + v.z * w.z + v.w * w.w;
        }
    }
#pragma unroll
    for (int e = 0; e < NE; e++)
#pragma unroll
        for (int o = 16; o; o >>= 1) acc[e] += __shfl_xor_sync(0xffffffffu, acc[e], o);

    if (lane == 0) {
        float m = acc[0]; int am = 0;
#pragma unroll
        for (int e = 1; e < NE; e++) if (acc[e] > m) { m = acc[e]; am = e; }
        float p[NE], s = 0.f;
#pragma unroll
        for (int e = 0; e < NE; e++) { p[e] = __expf(acc[e] - m); s += p[e]; }
        float inv = 1.f / s;
        g_top1[token] = am;
        g_topv[token] = p[am] * inv;
#pragma unroll
        for (int e = 0; e < NE; e++) atomicAdd(&blockP[e], p[e] * inv);
    }
    __syncthreads();
    if (tid < NE) g_blockP[blockIdx.x][tid] = blockP[tid];
}

// ---------------- deterministic scan + prob-sum reduction --------------------
__global__ void k_scan() {
    __shared__ int base[NE];
    __shared__ int wcnt[8][NE];
    int tid = threadIdx.x;
    int warp = tid >> 5, lane = tid & 31;
    unsigned ltmask = (1u << lane) - 1u;

    if (warp < NE) {
        float s = 0.f;
        for (int b = lane; b < NRB; b += 32) s += g_blockP[b][warp];
#pragma unroll
        for (int o = 16; o; o >>= 1) s += __shfl_xor_sync(0xffffffffu, s, o);
        if (lane == 0) g_sumP[warp] = s;
    }

    if (tid < NE) base[tid] = 0;
    __syncthreads();
    for (int w = 0; w < NTOK / 256; w++) {
        int t = w * 256 + tid;
        int e = g_top1[t];
        int myrank = 0;
#pragma unroll
        for (int ee = 0; ee < NE; ee++) {
            unsigned b = __ballot_sync(0xffffffffu, e == ee);
            if (lane == ee) wcnt[warp][ee] = __popc(b);
            if (e == ee) myrank = __popc(b & ltmask);
        }
        __syncthreads();
        int off = base[e];
        for (int w2 = 0; w2 < warp; w2++) off += wcnt[w2][e];
        int p = off + myrank;
        g_pos[t] = p;
        if (p < CAP) g_dest[e * CAP + p] = t;
        __syncthreads();
        if (tid < NE) {
            int s = 0;
#pragma unroll
            for (int w2 = 0; w2 < 8; w2++) s += wcnt[w2][tid];
            base[tid] += s;
        }
        __syncthreads();
    }
    if (tid < NE) {
        g_cnt[tid] = base[tid];
        g_rows[tid] = min(base[tid], CAP);
    }
}

// ---------------- GEMM1: mma.sync, h = silu(X Wg) * (X Wu) -------------------
// CTA: M=128 x N=128 (both), 512 threads; warps 0-7 gate, 8-15 up; 64x32 tiles
__global__ void __launch_bounds__(512, 1) k_gemm1() {
    extern __shared__ char smem[];
    __shared__ const __nv_bfloat16* tokp[128];

    int e = blockIdx.x / NBM;
    int m0 = (blockIdx.x % NBM) * 128;
    int rows = g_rows[e];
    if (m0 >= rows) return;
    int n0 = blockIdx.y * 128;
    int tid = threadIdx.x;
    int wid = tid >> 5, l = tid & 31;

    if (tid < 128) {
        int gr = m0 + tid;
        tokp[tid] = g_xb + (size_t)g_dest[e * CAP + ((gr < rows) ? gr : 0)] * DIM;
    }
    __syncthreads();

    uint32_t sb = s2u(smem);
    const __nv_bfloat16* gB = g_wgT + (size_t)e * FF * DIM + (size_t)n0 * DIM;
    const __nv_bfloat16* uB = g_wuT + (size_t)e * FF * DIM + (size_t)n0 * DIM;

    auto load_stage = [&](int s, int kb) {
        int k0 = kb * BK;
        uint32_t st = sb + s * ST1;
#pragma unroll
        for (int i = 0; i < 2; i++) {
            int idx = tid + i * 512;
            int r = idx >> 3, c = idx & 7;
            uint32_t o = r * 128 + ((c ^ (r & 7)) << 4);
            cp16(st + o, tokp[r] + k0 + c * 8);
            cp16(st + 16384 + o, gB + (size_t)r * DIM + k0 + c * 8);
            cp16(st + 32768 + o, uB + (size_t)r * DIM + k0 + c * 8);
        }
        cp_commit();
    };

    int mat = wid >> 3;          // 0 = gate, 1 = up
    int w   = wid & 7;
    int wm  = w >> 2;            // 0..1
    int wn  = w & 3;             // 0..3
    int grow = ((l >> 3) & 1) * 8 + (l & 7);
    int gk   = l >> 4;
    int rsw  = grow & 7;
    uint32_t rowA[4], rowB[2];
#pragma unroll
    for (int i = 0; i < 4; i++) rowA[i] = (wm * 64 + i * 16 + grow) * 128;
#pragma unroll
    for (int nf = 0; nf < 2; nf++)
        rowB[nf] = 16384 + mat * 16384 + (wn * 32 + nf * 16 + grow) * 128;

    float acc[4][4][4];
#pragma unroll
    for (int i = 0; i < 4; i++)
#pragma unroll
        for (int j = 0; j < 4; j++)
#pragma unroll
            for (int k = 0; k < 4; k++) acc[i][j][k] = 0.f;

    load_stage(0, 0);
    load_stage(1, 1);

    for (int it = 0; it < NIT1; it++) {
        int s = it % 3;
        if (it < NIT1 - 1) cp_wait1(); else cp_wait0();
        __syncthreads();
        if (it + 2 < NIT1) load_stage((it + 2) % 3, it + 2);
        uint32_t st = sb + s * ST1;
#pragma unroll
        for (int kk = 0; kk < 4; kk++) {
            int ck = kk * 2 + gk;
            uint32_t koff = (uint32_t)((ck ^ rsw) << 4);
            uint32_t a[4][4], bb[2][4];
#pragma unroll
            for (int i = 0; i < 4; i++) ldsm4(a[i], st + rowA[i] + koff);
#pragma unroll
            for (int nf = 0; nf < 2; nf++) ldsm4(bb[nf], st + rowB[nf] + koff);
#pragma unroll
            for (int i = 0; i < 4; i++) {
                mma16816(acc[i][0], a[i], bb[0][0], bb[0][2]);
                mma16816(acc[i][1], a[i], bb[0][1], bb[0][3]);
                mma16816(acc[i][2], a[i], bb[1][0], bb[1][2]);
                mma16816(acc[i][3], a[i], bb[1][1], bb[1][3]);
            }
        }
    }
    __syncthreads();

    // epilogue: up warps stage fp32 -> smem; gate warps silu*up -> bf16 smem;
    // all 512 threads stream uint4 stores to gmem.
    float* Cu = (float*)smem;                              // 128 x 136 fp32
    __nv_bfloat16* Hs = (__nv_bfloat16*)(smem + 73728);    // 128 x 136 bf16
    if (mat == 1) {
#pragma unroll
        for (int i = 0; i < 4; i++)
#pragma unroll
            for (int j = 0; j < 4; j++) {
                int r = wm * 64 + i * 16 + (l >> 2);
                int c = wn * 32 + j * 8 + (l & 3) * 2;
                Cu[r * 136 + c]           = acc[i][j][0];
                Cu[r * 136 + c + 1]       = acc[i][j][1];
                Cu[(r + 8) * 136 + c]     = acc[i][j][2];
                Cu[(r + 8) * 136 + c + 1] = acc[i][j][3];
            }
    }
    __syncthreads();
    if (mat == 0) {
#pragma unroll
        for (int i = 0; i < 4; i++)
#pragma unroll
            for (int j = 0; j < 4; j++) {
                int r = wm * 64 + i * 16 + (l >> 2);
                int c = wn * 32 + j * 8 + (l & 3) * 2;
#pragma unroll
                for (int h = 0; h < 2; h++) {
                    int rr = r + h * 8;
                    float g0 = acc[i][j][2 * h], g1 = acc[i][j][2 * h + 1];
                    float u0 = Cu[rr * 136 + c], u1 = Cu[rr * 136 + c + 1];
                    float h0 = g0 / (1.f + __expf(-g0)) * u0;
                    float h1 = g1 / (1.f + __expf(-g1)) * u1;
                    __nv_bfloat162 b2 = __floats2bfloat162_rn(h0, h1);
                    *(uint32_t*)(Hs + rr * 136 + c) = *(uint32_t*)&b2;
                }
            }
    }
    __syncthreads();
#pragma unroll
    for (int k = 0; k < 4; k++) {
        int idx = tid + k * 512;
        int r = idx >> 4, c8 = (idx & 15) * 8;
        if (m0 + r < rows)
            *(uint4*)(g_h + ((size_t)e * CAP + m0 + r) * FF + n0 + c8) =
                *(const uint4*)(Hs + r * 136 + c8);
    }
}

// ---------------- GEMM2: mma.sync, y = H Wd * prob, expert-order store --------
// CTA: M=128 x N=128, 256 threads, occupancy 2; warps 2m x 4n of 64x32
__global__ void __launch_bounds__(256, 2) k_gemm2() {
    extern __shared__ char smem[];
    __shared__ float sprob[128];

    int e = blockIdx.y / NBM;
    int m0 = (blockIdx.y % NBM) * 128;
    int rows = g_rows[e];
    if (m0 >= rows) return;
    int n0 = blockIdx.x * 128;
    int tid = threadIdx.x;
    int wid = tid >> 5, l = tid & 31;

    if (tid < 128) {
        int gr = m0 + tid;
        int tok = g_dest[e * CAP + ((gr < rows) ? gr : 0)];
        sprob[tid] = g_topv[tok];
    }
    __syncthreads();

    uint32_t sb = s2u(smem);
    const __nv_bfloat16* Ab = g_h + ((size_t)e * CAP + m0) * FF;
    const __nv_bfloat16* Bb = g_wdT + (size_t)e * DIM * FF + (size_t)n0 * FF;

    auto load_stage = [&](int s, int kb) {
        int k0 = kb * BK;
        uint32_t st = sb + s * ST2;
#pragma unroll
        for (int i = 0; i < 4; i++) {
            int idx = tid + i * 256;
            int r = idx >> 3, c = idx & 7;
            uint32_t o = r * 128 + ((c ^ (r & 7)) << 4);
            cp16(st + o, Ab + (size_t)r * FF + k0 + c * 8);
            cp16(st + 16384 + o, Bb + (size_t)r * FF + k0 + c * 8);
        }
        cp_commit();
    };

    int wm = wid >> 2;           // 0..1
    int wn = wid & 3;            // 0..3
    int grow = ((l >> 3) & 1) * 8 + (l & 7);
    int gk   = l >> 4;
    int rsw  = grow & 7;
    uint32_t rowA[4], rowB[2];
#pragma unroll
    for (int i = 0; i < 4; i++) rowA[i] = (wm * 64 + i * 16 + grow) * 128;
#pragma unroll
    for (int nf = 0; nf < 2; nf++)
        rowB[nf] = 16384 + (wn * 32 + nf * 16 + grow) * 128;

    float acc[4][4][4];
#pragma unroll
    for (int i = 0; i < 4; i++)
#pragma unroll
        for (int j = 0; j < 4; j++)
#pragma unroll
            for (int k = 0; k < 4; k++) acc[i][j][k] = 0.f;

    load_stage(0, 0);
    load_stage(1, 1);

    for (int it = 0; it < NIT2; it++) {
        int s = it % 3;
        if (it < NIT2 - 1) cp_wait1(); else cp_wait0();
        __syncthreads();
        if (it + 2 < NIT2) load_stage((it + 2) % 3, it + 2);
        uint32_t st = sb + s * ST2;
#pragma unroll
        for (int kk = 0; kk < 4; kk++) {
            int ck = kk * 2 + gk;
            uint32_t koff = (uint32_t)((ck ^ rsw) << 4);
            uint32_t a[4][4], bb[2][4];
#pragma unroll
            for (int i = 0; i < 4; i++) ldsm4(a[i], st + rowA[i] + koff);
#pragma unroll
            for (int nf = 0; nf < 2; nf++) ldsm4(bb[nf], st + rowB[nf] + koff);
#pragma unroll
            for (int i = 0; i < 4; i++) {
                mma16816(acc[i][0], a[i], bb[0][0], bb[0][2]);
                mma16816(acc[i][1], a[i], bb[0][1], bb[0][3]);
                mma16816(acc[i][2], a[i], bb[1][0], bb[1][2]);
                mma16816(acc[i][3], a[i], bb[1][1], bb[1][3]);
            }
        }
    }
    __syncthreads();

    // stage fp32 result, then contiguous prob-scaled store (expert order)
    float* Cs = (float*)smem;     // 128 x 136 fp32
#pragma unroll
    for (int i = 0; i < 4; i++)
#pragma unroll
        for (int j = 0; j < 4; j++) {
            int r = wm * 64 + i * 16 + (l >> 2);
            int c = wn * 32 + j * 8 + (l & 3) * 2;
            Cs[r * 136 + c]           = acc[i][j][0];
            Cs[r * 136 + c + 1]       = acc[i][j][1];
            Cs[(r + 8) * 136 + c]     = acc[i][j][2];
            Cs[(r + 8) * 136 + c + 1] = acc[i][j][3];
        }
    __syncthreads();

    float* ybase = g_y + ((size_t)e * CAP + m0) * DIM + n0;
#pragma unroll
    for (int k = 0; k < 16; k++) {
        int idx = tid + k * 256;
        int r = idx >> 5, cc = (idx & 31) * 4;
        float p = sprob[r];
        float4 v;
        v.x = Cs[r * 136 + cc]     * p;
        v.y = Cs[r * 136 + cc + 1] * p;
        v.z = Cs[r * 136 + cc + 2] * p;
        v.w = Cs[r * 136 + cc + 3] * p;
        *(float4*)(ybase + (size_t)r * DIM + cc) = v;
    }
}

// ---------------- residual + LayerNorm (gathers expert-order y) ---------------
__global__ void __launch_bounds__(256) k_ln(const float* __restrict__ x,
                                            const float* __restrict__ lng,
                                            const float* __restrict__ lnb,
                                            float* __restrict__ out, int out_size) {
    int t = blockIdx.x, tid = threadIdx.x;
    if (t == 0 && tid == 0) {
        float lb = 0.f;
        const float invN = 1.f / (float)NTOK;
#pragma unroll
        for (int e = 0; e < NE; e++)
            lb += ((float)g_cnt[e] * invN) * (g_sumP[e] * invN);
        lb *= (float)NE;
        if (out_size > NTOK * DIM) out[NTOK * DIM] = lb;
    }
    int e = g_top1[t];
    int pos = g_pos[t];
    bool keep = pos < CAP;
    const float* xr = x + (size_t)t * DIM;
    const float* fr = g_y + ((size_t)e * CAP + (keep ? pos : 0)) * DIM;
    float v[4], s = 0.f, s2 = 0.f;
#pragma unroll
    for (int i = 0; i < 4; i++) {
        int c = tid + i * 256;
        float r = xr[c] + (keep ? fr[c] : 0.f);
        v[i] = r; s += r; s2 += r * r;
    }
#pragma unroll
    for (int o = 16; o; o >>= 1) {
        s  += __shfl_xor_sync(0xffffffffu, s, o);
        s2 += __shfl_xor_sync(0xffffffffu, s2, o);
    }
    __shared__ float sh[16];
    int w = tid >> 5;
    if ((tid & 31) == 0) { sh[w] = s; sh[8 + w] = s2; }
    __syncthreads();
    float S = 0.f, S2 = 0.f;
#pragma unroll
    for (int i = 0; i < 8; i++) { S += sh[i]; S2 += sh[8 + i]; }
    float mu = S * (1.f / DIM);
    float var = S2 * (1.f / DIM) - mu * mu;
    float inv = rsqrtf(var + 1e-5f);
    float* orow = out + (size_t)t * DIM;
#pragma unroll
    for (int i = 0; i < 4; i++) {
        int c = tid + i * 256;
        orow[c] = (v[i] - mu) * inv * lng[c] + lnb[c];
    }
}

// ---------------- launch --------------------------------------------------------
extern "C" void kernel_launch(void* const* d_in, const int* in_sizes, int n_in,
                              void* d_out, int out_size) {
    const float* x   = (const float*)d_in[0];
    const float* rw  = (const float*)d_in[1];
    const float* gw  = (const float*)d_in[2];
    const float* uw  = (const float*)d_in[3];
    const float* dw  = (const float*)d_in[4];
    const float* lng = (const float*)d_in[5];
    const float* lnb = (const float*)d_in[6];
    float* out = (float*)d_out;
    (void)in_sizes; (void)n_in;

    static bool init_done = false;
    static cudaStream_t s1, s2, s3;
    static cudaEvent_t evFork, evJoin1, evJoin2, evJoin3;
    if (!init_done) {
        cudaFuncSetAttribute(k_gemm1, cudaFuncAttributeMaxDynamicSharedMemorySize, 3 * ST1);
        cudaFuncSetAttribute(k_gemm2, cudaFuncAttributeMaxDynamicSharedMemorySize, 3 * ST2);
        cudaStreamCreateWithFlags(&s1, cudaStreamNonBlocking);
        cudaStreamCreateWithFlags(&s2, cudaStreamNonBlocking);
        cudaStreamCreateWithFlags(&s3, cudaStreamNonBlocking);
        cudaEventCreateWithFlags(&evFork, cudaEventDisableTiming);
        cudaEventCreateWithFlags(&evJoin1, cudaEventDisableTiming);
        cudaEventCreateWithFlags(&evJoin2, cudaEventDisableTiming);
        cudaEventCreateWithFlags(&evJoin3, cudaEventDisableTiming);
        init_done = true;
    }

    __nv_bfloat16* wgT; cudaGetSymbolAddress((void**)&wgT, g_wgT);
    __nv_bfloat16* wuT; cudaGetSymbolAddress((void**)&wuT, g_wuT);
    __nv_bfloat16* wdT; cudaGetSymbolAddress((void**)&wdT, g_wdT);

    // anchor on default stream (capture origin), then fork to 3 side streams
    k_anchor<<<1, 32>>>();
    cudaEventRecord(evFork, 0);
    cudaStreamWaitEvent(s1, evFork, 0);
    cudaStreamWaitEvent(s2, evFork, 0);
    cudaStreamWaitEvent(s3, evFork, 0);

    k_transpose<<<dim3(FF / 32, DIM / 64, NE), 256, 0, s1>>>(gw, wgT, DIM, FF);
    cudaEventRecord(evJoin1, s1);
    k_transpose<<<dim3(FF / 32, DIM / 64, NE), 256, 0, s2>>>(uw, wuT, DIM, FF);
    cudaEventRecord(evJoin2, s2);
    k_transpose<<<dim3(DIM / 32, FF / 64, NE), 256, 0, s3>>>(dw, wdT, FF, DIM);
    cudaEventRecord(evJoin3, s3);

    // token-side pipeline on default stream
    k_router<<<NRB, 256>>>(x, rw);
    k_scan<<<1, 256>>>();

    cudaStreamWaitEvent(0, evJoin1, 0);
    cudaStreamWaitEvent(0, evJoin2, 0);
    cudaStreamWaitEvent(0, evJoin3, 0);

    k_gemm1<<<dim3(NE * NBM, FF / 128), 512, 3 * ST1>>>();
    k_gemm2<<<dim3(DIM / 128, NE * NBM), 256, 3 * ST2>>>();

    k_ln<<<NTOK, 256>>>(x, lng, lnb, out, out_size);
}

// round 17
// speedup vs baseline: 1.0729x; 1.0037x over previous
#include <cuda_runtime.h>
#include <cuda_bf16.h>
#include <cstdint>

#define NTOK 16384
#define DIM  1024
#define FF   4096
#define NE   8
#define CAP  2560
#define NBM  20            // CAP / 128
#define BK   64
#define NIT1 (DIM / BK)    // 16
#define NIT2 (FF / BK)     // 64
#define ST1  49152         // stage bytes gemm1: A 16K + Bg 16K + Bu 16K
#define ST2  32768         // stage bytes gemm2: A 16K + B 16K
#define NRB  (NTOK / 8)    // router blocks = 2048

// ---------------- scratch globals -------------------------------------------
__device__ __nv_bfloat16 g_xb[(size_t)NTOK * DIM];
__device__ __nv_bfloat16 g_wgT[(size_t)NE * FF * DIM];  // [E][F][D]
__device__ __nv_bfloat16 g_wuT[(size_t)NE * FF * DIM];  // [E][F][D]
__device__ __nv_bfloat16 g_wdT[(size_t)NE * DIM * FF];  // [E][D][F]
__device__ __nv_bfloat16 g_h[(size_t)NE * CAP * FF];
__device__ float g_y[(size_t)NE * CAP * DIM];           // expert-order FFN output
__device__ int   g_top1[NTOK];
__device__ int   g_pos[NTOK];
__device__ float g_topv[NTOK];
__device__ int   g_dest[NE * CAP];
__device__ int   g_rows[NE];
__device__ int   g_cnt[NE];
__device__ float g_sumP[NE];
__device__ float g_blockP[NRB][NE];

// ---------------- PTX helpers ------------------------------------------------
__device__ __forceinline__ uint32_t s2u(const void* p) {
    return (uint32_t)__cvta_generic_to_shared(p);
}
__device__ __forceinline__ void cp16(uint32_t dst, const void* src) {
    asm volatile("cp.async.cg.shared.global [%0], [%1], 16;\n" :: "r"(dst), "l"(src));
}
__device__ __forceinline__ void cp_commit() { asm volatile("cp.async.commit_group;\n" ::: "memory"); }
__device__ __forceinline__ void cp_wait0()  { asm volatile("cp.async.wait_group 0;\n" ::: "memory"); }
__device__ __forceinline__ void cp_wait1()  { asm volatile("cp.async.wait_group 1;\n" ::: "memory"); }

__device__ __forceinline__ void ldsm4(uint32_t (&d)[4], uint32_t addr) {
    asm volatile("ldmatrix.sync.aligned.m8n8.x4.shared.b16 {%0,%1,%2,%3}, [%4];"
        : "=r"(d[0]), "=r"(d[1]), "=r"(d[2]), "=r"(d[3]) : "r"(addr));
}
__device__ __forceinline__ void mma16816(float (&c)[4], const uint32_t (&a)[4],
                                         uint32_t b0, uint32_t b1) {
    asm volatile("mma.sync.aligned.m16n8k16.row.col.f32.bf16.bf16.f32 "
        "{%0,%1,%2,%3}, {%4,%5,%6,%7}, {%8,%9}, {%0,%1,%2,%3};"
        : "+f"(c[0]), "+f"(c[1]), "+f"(c[2]), "+f"(c[3])
        : "r"(a[0]), "r"(a[1]), "r"(a[2]), "r"(a[3]), "r"(b0), "r"(b1));
}

// ---------------- anchor (capture origin) ------------------------------------
__global__ void k_anchor() {}

// ---------------- transpose: fp32 [E][R][C] -> bf16 [E][C][R] -----------------
// 64-row tiles, packed bf16x2 stores (4B per thread, fully coalesced)
__global__ void __launch_bounds__(256) k_transpose(const float* __restrict__ in,
                                                   __nv_bfloat16* __restrict__ out,
                                                   int R, int C) {
    __shared__ float tile[64][33];
    int e = blockIdx.z;
    int c0 = blockIdx.x * 32;
    int r0 = blockIdx.y * 64;
    int tx = threadIdx.x & 31, ty = threadIdx.x >> 5;   // ty 0..7
    const float* src = in + (size_t)e * R * C;
    __nv_bfloat16* dst = out + (size_t)e * C * R;
#pragma unroll
    for (int k = 0; k < 8; k++)
        tile[ty + 8 * k][tx] = src[(size_t)(r0 + ty + 8 * k) * C + c0 + tx];
    __syncthreads();
#pragma unroll
    for (int k = 0; k < 4; k++) {
        int col = ty + 8 * k;    // 0..31
        __nv_bfloat162 b2 = __floats2bfloat162_rn(tile[2 * tx][col], tile[2 * tx + 1][col]);
        *(__nv_bfloat162*)(dst + (size_t)(c0 + col) * R + r0 + 2 * tx) = b2;
    }
}

// ---------------- router (converts x -> bf16), MLP-8 loads --------------------
__global__ void __launch_bounds__(256) k_router(const float* __restrict__ x,
                                                const float* __restrict__ rw) {
    __shared__ float rwsT[NE][DIM];    // transposed: conflict-free float4 reads
    __shared__ float blockP[NE];
    int tid = threadIdx.x;
    for (int i = tid; i < DIM * NE; i += 256) {
        int d = i >> 3, e = i & 7;
        rwsT[e][d] = rw[i];
    }
    if (tid < NE) blockP[tid] = 0.f;
    __syncthreads();

    int warp = tid >> 5, lane = tid & 31;
    int token = blockIdx.x * 8 + warp;

    const float* xr = x + (size_t)token * DIM;
    __nv_bfloat16* xb = g_xb + (size_t)token * DIM;

    // batch all 8 row-chunks into registers (MLP = 8)
    float4 v[8];
#pragma unroll
    for (int i = 0; i < 8; i++)
        v[i] = *(const float4*)(xr + lane * 4 + i * 128);

    float acc[NE];
#pragma unroll
    for (int e = 0; e < NE; e++) acc[e] = 0.f;
#pragma unroll
    for (int i = 0; i < 8; i++) {
        int base = lane * 4 + i * 128;
        *(__nv_bfloat162*)(xb + base)     = __floats2bfloat162_rn(v[i].x, v[i].y);
        *(__nv_bfloat162*)(xb + base + 2) = __floats2bfloat162_rn(v[i].z, v[i].w);
#pragma unroll
        for (int e = 0; e < NE; e++) {
            float4 w = *(const float4*)(&rwsT[e][base]);
            acc[e] += v[i].x * w.x + v[i].y * w.y + v[i].z * w.z + v[i].w * w.w;
        }
    }
#pragma unroll
    for (int e = 0; e < NE; e++)
#pragma unroll
        for (int o = 16; o; o >>= 1) acc[e] += __shfl_xor_sync(0xffffffffu, acc[e], o);

    if (lane == 0) {
        float m = acc[0]; int am = 0;
#pragma unroll
        for (int e = 1; e < NE; e++) if (acc[e] > m) { m = acc[e]; am = e; }
        float p[NE], s = 0.f;
#pragma unroll
        for (int e = 0; e < NE; e++) { p[e] = __expf(acc[e] - m); s += p[e]; }
        float inv = 1.f / s;
        g_top1[token] = am;
        g_topv[token] = p[am] * inv;
#pragma unroll
        for (int e = 0; e < NE; e++) atomicAdd(&blockP[e], p[e] * inv);
    }
    __syncthreads();
    if (tid < NE) g_blockP[blockIdx.x][tid] = blockP[tid];
}

// ---------------- deterministic scan + prob-sum reduction --------------------
__global__ void k_scan() {
    __shared__ int base[NE];
    __shared__ int wcnt[8][NE];
    int tid = threadIdx.x;
    int warp = tid >> 5, lane = tid & 31;
    unsigned ltmask = (1u << lane) - 1u;

    if (warp < NE) {
        float s = 0.f;
        for (int b = lane; b < NRB; b += 32) s += g_blockP[b][warp];
#pragma unroll
        for (int o = 16; o; o >>= 1) s += __shfl_xor_sync(0xffffffffu, s, o);
        if (lane == 0) g_sumP[warp] = s;
    }

    if (tid < NE) base[tid] = 0;
    __syncthreads();
    for (int w = 0; w < NTOK / 256; w++) {
        int t = w * 256 + tid;
        int e = g_top1[t];
        int myrank = 0;
#pragma unroll
        for (int ee = 0; ee < NE; ee++) {
            unsigned b = __ballot_sync(0xffffffffu, e == ee);
            if (lane == ee) wcnt[warp][ee] = __popc(b);
            if (e == ee) myrank = __popc(b & ltmask);
        }
        __syncthreads();
        int off = base[e];
        for (int w2 = 0; w2 < warp; w2++) off += wcnt[w2][e];
        int p = off + myrank;
        g_pos[t] = p;
        if (p < CAP) g_dest[e * CAP + p] = t;
        __syncthreads();
        if (tid < NE) {
            int s = 0;
#pragma unroll
            for (int w2 = 0; w2 < 8; w2++) s += wcnt[w2][tid];
            base[tid] += s;
        }
        __syncthreads();
    }
    if (tid < NE) {
        g_cnt[tid] = base[tid];
        g_rows[tid] = min(base[tid], CAP);
    }
}

// ---------------- GEMM1: mma.sync, h = silu(X Wg) * (X Wu) -------------------
// CTA: M=128 x N=128 (both), 512 threads; warps 0-7 gate, 8-15 up; 64x32 tiles
__global__ void __launch_bounds__(512, 1) k_gemm1() {
    extern __shared__ char smem[];
    __shared__ const __nv_bfloat16* tokp[128];

    int e = blockIdx.x / NBM;
    int m0 = (blockIdx.x % NBM) * 128;
    int rows = g_rows[e];
    if (m0 >= rows) return;
    int n0 = blockIdx.y * 128;
    int tid = threadIdx.x;
    int wid = tid >> 5, l = tid & 31;

    if (tid < 128) {
        int gr = m0 + tid;
        tokp[tid] = g_xb + (size_t)g_dest[e * CAP + ((gr < rows) ? gr : 0)] * DIM;
    }
    __syncthreads();

    uint32_t sb = s2u(smem);
    const __nv_bfloat16* gB = g_wgT + (size_t)e * FF * DIM + (size_t)n0 * DIM;
    const __nv_bfloat16* uB = g_wuT + (size_t)e * FF * DIM + (size_t)n0 * DIM;

    auto load_stage = [&](int s, int kb) {
        int k0 = kb * BK;
        uint32_t st = sb + s * ST1;
#pragma unroll
        for (int i = 0; i < 2; i++) {
            int idx = tid + i * 512;
            int r = idx >> 3, c = idx & 7;
            uint32_t o = r * 128 + ((c ^ (r & 7)) << 4);
            cp16(st + o, tokp[r] + k0 + c * 8);
            cp16(st + 16384 + o, gB + (size_t)r * DIM + k0 + c * 8);
            cp16(st + 32768 + o, uB + (size_t)r * DIM + k0 + c * 8);
        }
        cp_commit();
    };

    int mat = wid >> 3;          // 0 = gate, 1 = up
    int w   = wid & 7;
    int wm  = w >> 2;            // 0..1
    int wn  = w & 3;             // 0..3
    int grow = ((l >> 3) & 1) * 8 + (l & 7);
    int gk   = l >> 4;
    int rsw  = grow & 7;
    uint32_t rowA[4], rowB[2];
#pragma unroll
    for (int i = 0; i < 4; i++) rowA[i] = (wm * 64 + i * 16 + grow) * 128;
#pragma unroll
    for (int nf = 0; nf < 2; nf++)
        rowB[nf] = 16384 + mat * 16384 + (wn * 32 + nf * 16 + grow) * 128;

    float acc[4][4][4];
#pragma unroll
    for (int i = 0; i < 4; i++)
#pragma unroll
        for (int j = 0; j < 4; j++)
#pragma unroll
            for (int k = 0; k < 4; k++) acc[i][j][k] = 0.f;

    load_stage(0, 0);
    load_stage(1, 1);

    for (int it = 0; it < NIT1; it++) {
        int s = it % 3;
        if (it < NIT1 - 1) cp_wait1(); else cp_wait0();
        __syncthreads();
        if (it + 2 < NIT1) load_stage((it + 2) % 3, it + 2);
        uint32_t st = sb + s * ST1;
#pragma unroll
        for (int kk = 0; kk < 4; kk++) {
            int ck = kk * 2 + gk;
            uint32_t koff = (uint32_t)((ck ^ rsw) << 4);
            uint32_t a[4][4], bb[2][4];
#pragma unroll
            for (int i = 0; i < 4; i++) ldsm4(a[i], st + rowA[i] + koff);
#pragma unroll
            for (int nf = 0; nf < 2; nf++) ldsm4(bb[nf], st + rowB[nf] + koff);
#pragma unroll
            for (int i = 0; i < 4; i++) {
                mma16816(acc[i][0], a[i], bb[0][0], bb[0][2]);
                mma16816(acc[i][1], a[i], bb[0][1], bb[0][3]);
                mma16816(acc[i][2], a[i], bb[1][0], bb[1][2]);
                mma16816(acc[i][3], a[i], bb[1][1], bb[1][3]);
            }
        }
    }
    __syncthreads();

    // epilogue: up warps stage fp32 -> smem; gate warps silu*up -> bf16 smem;
    // all 512 threads stream uint4 stores to gmem.
    float* Cu = (float*)smem;                              // 128 x 136 fp32
    __nv_bfloat16* Hs = (__nv_bfloat16*)(smem + 73728);    // 128 x 136 bf16
    if (mat == 1) {
#pragma unroll
        for (int i = 0; i < 4; i++)
#pragma unroll
            for (int j = 0; j < 4; j++) {
                int r = wm * 64 + i * 16 + (l >> 2);
                int c = wn * 32 + j * 8 + (l & 3) * 2;
                Cu[r * 136 + c]           = acc[i][j][0];
                Cu[r * 136 + c + 1]       = acc[i][j][1];
                Cu[(r + 8) * 136 + c]     = acc[i][j][2];
                Cu[(r + 8) * 136 + c + 1] = acc[i][j][3];
            }
    }
    __syncthreads();
    if (mat == 0) {
#pragma unroll
        for (int i = 0; i < 4; i++)
#pragma unroll
            for (int j = 0; j < 4; j++) {
                int r = wm * 64 + i * 16 + (l >> 2);
                int c = wn * 32 + j * 8 + (l & 3) * 2;
#pragma unroll
                for (int h = 0; h < 2; h++) {
                    int rr = r + h * 8;
                    float g0 = acc[i][j][2 * h], g1 = acc[i][j][2 * h + 1];
                    float u0 = Cu[rr * 136 + c], u1 = Cu[rr * 136 + c + 1];
                    float h0 = g0 / (1.f + __expf(-g0)) * u0;
                    float h1 = g1 / (1.f + __expf(-g1)) * u1;
                    __nv_bfloat162 b2 = __floats2bfloat162_rn(h0, h1);
                    *(uint32_t*)(Hs + rr * 136 + c) = *(uint32_t*)&b2;
                }
            }
    }
    __syncthreads();
#pragma unroll
    for (int k = 0; k < 4; k++) {
        int idx = tid + k * 512;
        int r = idx >> 4, c8 = (idx & 15) * 8;
        if (m0 + r < rows)
            *(uint4*)(g_h + ((size_t)e * CAP + m0 + r) * FF + n0 + c8) =
                *(const uint4*)(Hs + r * 136 + c8);
    }
}

// ---------------- GEMM2: mma.sync, y = H Wd * prob, expert-order store --------
// CTA: M=128 x N=128, 256 threads, occupancy 2; warps 2m x 4n of 64x32
__global__ void __launch_bounds__(256, 2) k_gemm2() {
    extern __shared__ char smem[];
    __shared__ float sprob[128];

    int e = blockIdx.y / NBM;
    int m0 = (blockIdx.y % NBM) * 128;
    int rows = g_rows[e];
    if (m0 >= rows) return;
    int n0 = blockIdx.x * 128;
    int tid = threadIdx.x;
    int wid = tid >> 5, l = tid & 31;

    if (tid < 128) {
        int gr = m0 + tid;
        int tok = g_dest[e * CAP + ((gr < rows) ? gr : 0)];
        sprob[tid] = g_topv[tok];
    }
    __syncthreads();

    uint32_t sb = s2u(smem);
    const __nv_bfloat16* Ab = g_h + ((size_t)e * CAP + m0) * FF;
    const __nv_bfloat16* Bb = g_wdT + (size_t)e * DIM * FF + (size_t)n0 * FF;

    auto load_stage = [&](int s, int kb) {
        int k0 = kb * BK;
        uint32_t st = sb + s * ST2;
#pragma unroll
        for (int i = 0; i < 4; i++) {
            int idx = tid + i * 256;
            int r = idx >> 3, c = idx & 7;
            uint32_t o = r * 128 + ((c ^ (r & 7)) << 4);
            cp16(st + o, Ab + (size_t)r * FF + k0 + c * 8);
            cp16(st + 16384 + o, Bb + (size_t)r * FF + k0 + c * 8);
        }
        cp_commit();
    };

    int wm = wid >> 2;           // 0..1
    int wn = wid & 3;            // 0..3
    int grow = ((l >> 3) & 1) * 8 + (l & 7);
    int gk   = l >> 4;
    int rsw  = grow & 7;
    uint32_t rowA[4], rowB[2];
#pragma unroll
    for (int i = 0; i < 4; i++) rowA[i] = (wm * 64 + i * 16 + grow) * 128;
#pragma unroll
    for (int nf = 0; nf < 2; nf++)
        rowB[nf] = 16384 + (wn * 32 + nf * 16 + grow) * 128;

    float acc[4][4][4];
#pragma unroll
    for (int i = 0; i < 4; i++)
#pragma unroll
        for (int j = 0; j < 4; j++)
#pragma unroll
            for (int k = 0; k < 4; k++) acc[i][j][k] = 0.f;

    load_stage(0, 0);
    load_stage(1, 1);

    for (int it = 0; it < NIT2; it++) {
        int s = it % 3;
        if (it < NIT2 - 1) cp_wait1(); else cp_wait0();
        __syncthreads();
        if (it + 2 < NIT2) load_stage((it + 2) % 3, it + 2);
        uint32_t st = sb + s * ST2;
#pragma unroll
        for (int kk = 0; kk < 4; kk++) {
            int ck = kk * 2 + gk;
            uint32_t koff = (uint32_t)((ck ^ rsw) << 4);
            uint32_t a[4][4], bb[2][4];
#pragma unroll
            for (int i = 0; i < 4; i++) ldsm4(a[i], st + rowA[i] + koff);
#pragma unroll
            for (int nf = 0; nf < 2; nf++) ldsm4(bb[nf], st + rowB[nf] + koff);
#pragma unroll
            for (int i = 0; i < 4; i++) {
                mma16816(acc[i][0], a[i], bb[0][0], bb[0][2]);
                mma16816(acc[i][1], a[i], bb[0][1], bb[0][3]);
                mma16816(acc[i][2], a[i], bb[1][0], bb[1][2]);
                mma16816(acc[i][3], a[i], bb[1][1], bb[1][3]);
            }
        }
    }
    __syncthreads();

    // stage fp32 result, then contiguous prob-scaled store (expert order)
    float* Cs = (float*)smem;     // 128 x 136 fp32
#pragma unroll
    for (int i = 0; i < 4; i++)
#pragma unroll
        for (int j = 0; j < 4; j++) {
            int r = wm * 64 + i * 16 + (l >> 2);
            int c = wn * 32 + j * 8 + (l & 3) * 2;
            Cs[r * 136 + c]           = acc[i][j][0];
            Cs[r * 136 + c + 1]       = acc[i][j][1];
            Cs[(r + 8) * 136 + c]     = acc[i][j][2];
            Cs[(r + 8) * 136 + c + 1] = acc[i][j][3];
        }
    __syncthreads();

    float* ybase = g_y + ((size_t)e * CAP + m0) * DIM + n0;
#pragma unroll
    for (int k = 0; k < 16; k++) {
        int idx = tid + k * 256;
        int r = idx >> 5, cc = (idx & 31) * 4;
        float p = sprob[r];
        float4 v;
        v.x = Cs[r * 136 + cc]     * p;
        v.y = Cs[r * 136 + cc + 1] * p;
        v.z = Cs[r * 136 + cc + 2] * p;
        v.w = Cs[r * 136 + cc + 3] * p;
        *(float4*)(ybase + (size_t)r * DIM + cc) = v;
    }
}

// ---------------- residual + LayerNorm (gathers expert-order y) ---------------
__global__ void __launch_bounds__(256) k_ln(const float* __restrict__ x,
                                            const float* __restrict__ lng,
                                            const float* __restrict__ lnb,
                                            float* __restrict__ out, int out_size) {
    int t = blockIdx.x, tid = threadIdx.x;
    if (t == 0 && tid == 0) {
        float lb = 0.f;
        const float invN = 1.f / (float)NTOK;
#pragma unroll
        for (int e = 0; e < NE; e++)
            lb += ((float)g_cnt[e] * invN) * (g_sumP[e] * invN);
        lb *= (float)NE;
        if (out_size > NTOK * DIM) out[NTOK * DIM] = lb;
    }
    int e = g_top1[t];
    int pos = g_pos[t];
    bool keep = pos < CAP;
    const float* xr = x + (size_t)t * DIM;
    const float* fr = g_y + ((size_t)e * CAP + (keep ? pos : 0)) * DIM;
    float v[4], s = 0.f, s2 = 0.f;
#pragma unroll
    for (int i = 0; i < 4; i++) {
        int c = tid + i * 256;
        float r = xr[c] + (keep ? fr[c] : 0.f);
        v[i] = r; s += r; s2 += r * r;
    }
#pragma unroll
    for (int o = 16; o; o >>= 1) {
        s  += __shfl_xor_sync(0xffffffffu, s, o);
        s2 += __shfl_xor_sync(0xffffffffu, s2, o);
    }
    __shared__ float sh[16];
    int w = tid >> 5;
    if ((tid & 31) == 0) { sh[w] = s; sh[8 + w] = s2; }
    __syncthreads();
    float S = 0.f, S2 = 0.f;
#pragma unroll
    for (int i = 0; i < 8; i++) { S += sh[i]; S2 += sh[8 + i]; }
    float mu = S * (1.f / DIM);
    float var = S2 * (1.f / DIM) - mu * mu;
    float inv = rsqrtf(var + 1e-5f);
    float* orow = out + (size_t)t * DIM;
#pragma unroll
    for (int i = 0; i < 4; i++) {
        int c = tid + i * 256;
        orow[c] = (v[i] - mu) * inv * lng[c] + lnb[c];
    }
}

// ---------------- launch --------------------------------------------------------
extern "C" void kernel_launch(void* const* d_in, const int* in_sizes, int n_in,
                              void* d_out, int out_size) {
    const float* x   = (const float*)d_in[0];
    const float* rw  = (const float*)d_in[1];
    const float* gw  = (const float*)d_in[2];
    const float* uw  = (const float*)d_in[3];
    const float* dw  = (const float*)d_in[4];
    const float* lng = (const float*)d_in[5];
    const float* lnb = (const float*)d_in[6];
    float* out = (float*)d_out;
    (void)in_sizes; (void)n_in;

    static bool init_done = false;
    static cudaStream_t s1, s2, s3;
    static cudaEvent_t evFork, evJoin1, evJoin2, evJoin3;
    if (!init_done) {
        cudaFuncSetAttribute(k_gemm1, cudaFuncAttributeMaxDynamicSharedMemorySize, 3 * ST1);
        cudaFuncSetAttribute(k_gemm2, cudaFuncAttributeMaxDynamicSharedMemorySize, 3 * ST2);
        cudaStreamCreateWithFlags(&s1, cudaStreamNonBlocking);
        cudaStreamCreateWithFlags(&s2, cudaStreamNonBlocking);
        cudaStreamCreateWithFlags(&s3, cudaStreamNonBlocking);
        cudaEventCreateWithFlags(&evFork, cudaEventDisableTiming);
        cudaEventCreateWithFlags(&evJoin1, cudaEventDisableTiming);
        cudaEventCreateWithFlags(&evJoin2, cudaEventDisableTiming);
        cudaEventCreateWithFlags(&evJoin3, cudaEventDisableTiming);
        init_done = true;
    }

    __nv_bfloat16* wgT; cudaGetSymbolAddress((void**)&wgT, g_wgT);
    __nv_bfloat16* wuT; cudaGetSymbolAddress((void**)&wuT, g_wuT);
    __nv_bfloat16* wdT; cudaGetSymbolAddress((void**)&wdT, g_wdT);

    // anchor on default stream (capture origin), then fork to 3 side streams
    k_anchor<<<1, 32>>>();
    cudaEventRecord(evFork, 0);
    cudaStreamWaitEvent(s1, evFork, 0);
    cudaStreamWaitEvent(s2, evFork, 0);
    cudaStreamWaitEvent(s3, evFork, 0);

    k_transpose<<<dim3(FF / 32, DIM / 64, NE), 256, 0, s1>>>(gw, wgT, DIM, FF);
    cudaEventRecord(evJoin1, s1);
    k_transpose<<<dim3(FF / 32, DIM / 64, NE), 256, 0, s2>>>(uw, wuT, DIM, FF);
    cudaEventRecord(evJoin2, s2);
    k_transpose<<<dim3(DIM / 32, FF / 64, NE), 256, 0, s3>>>(dw, wdT, FF, DIM);
    cudaEventRecord(evJoin3, s3);

    // token-side pipeline on default stream
    k_router<<<NRB, 256>>>(x, rw);
    k_scan<<<1, 256>>>();

    cudaStreamWaitEvent(0, evJoin1, 0);
    cudaStreamWaitEvent(0, evJoin2, 0);
    cudaStreamWaitEvent(0, evJoin3, 0);

    k_gemm1<<<dim3(NE * NBM, FF / 128), 512, 3 * ST1>>>();
    k_gemm2<<<dim3(DIM / 128, NE * NBM), 256, 3 * ST2>>>();

    k_ln<<<NTOK, 256>>>(x, lng, lnb, out, out_size);
}